// round 5
// baseline (speedup 1.0000x reference)
#include <cuda_runtime.h>
#include <mma.h>
#include <cstdint>

using namespace nvcuda;

// Problem constants
#define Bq 32
#define Sq 2048
#define Dq 512
#define Hq 32
#define NTOK   (Bq * Sq)      // 65536
#define NSLICE (NTOK / 64)    // 1024 slices of 64 tokens (batch-aligned)

// ---------------- shared layout (float offsets) ----------------
#define XSTRIDE 520           // X row stride (pad 8 -> conflict-free)
#define WSTRIDE 40            // Ws row stride
#define SM_MODE 0             // mask dtype (int)
#define SM_WFS  8             // per-warp wf sums [8]
#define SM_HT   16            // Ht swizzled 32x32 -> ends 1040
#define SM_WS   1040          // Ws[64][40]        -> ends 3600
#define SM_PN   3600          // Pn[32][520] (B col-major) -> ends 20240
#define SM_X    20240         // X[64][520]        -> ends 53520
#define SM_FLOATS 53520
#define SMEM_BYTES (SM_FLOATS * 4)   // 214080

#define RSCALE 0.17677669529663687f  // 1/sqrt(32)

// ---------------- scratch (overwritten every run; no zeroing needed) ------
__device__ float g_part[NSLICE][Dq];  // per-slice weighted partial sums
__device__ float g_wfs[NSLICE];       // per-slice weight sums

// ---------------- helpers ----------------
__device__ __forceinline__ void fma2(unsigned long long& d,
                                     unsigned long long a,
                                     unsigned long long b) {
    asm("fma.rn.f32x2 %0, %1, %2, %3;" : "=l"(d) : "l"(a), "l"(b), "l"(d));
}
__device__ __forceinline__ float2 upk(unsigned long long v) {
    float2 r;
    asm("mov.b64 {%0, %1}, %2;" : "=f"(r.x), "=f"(r.y) : "l"(v));
    return r;
}
__device__ __forceinline__ float sigmoidf(float v) {
    return 1.0f / (1.0f + __expf(-v));
}
__device__ __forceinline__ bool mask_on(const void* mask, int mm, int t) {
    if (mm == 1) return ((const int*)mask)[t] != 0;
    if (mm == 2) return ((const float*)mask)[t] != 0.0f;
    return ((const unsigned char*)mask)[t] != 0;
}
__device__ __forceinline__ int detect_mode(const unsigned int* m, int lane) {
    bool ai = true, af = true;
#pragma unroll
    for (int k = 0; k < 8; ++k) {
        unsigned v = m[lane * 8 + k];
        ai &= (v <= 1u);
        af &= (v == 0u || v == 0x3F800000u);
    }
    unsigned bi = __ballot_sync(0xffffffffu, ai);
    unsigned bf = __ballot_sync(0xffffffffu, af);
    return (bi == 0xffffffffu) ? 1 : ((bf == 0xffffffffu) ? 2 : 0);
}

// ---------------- kernel: main (persistent, WMMA tf32) ----------------
__global__ void __launch_bounds__(256) k_main(const float* __restrict__ inp,
                                              const void* __restrict__ mask,
                                              const float* __restrict__ proj,
                                              const float* __restrict__ hid,
                                              const float* __restrict__ ev) {
    extern __shared__ float sm[];
    const int tid  = threadIdx.x;
    const int lane = tid & 31;
    const int wid  = tid >> 5;
    const int tg   = lane >> 3;
    const int hg   = lane & 7;
    const int mi   = wid >> 1;        // token-tile 0..3
    const int ni   = wid & 1;         // n-tile 0..1

    // ---- prologue: detect mask mode, stage Pn + Ht ----
    if (wid == 0) {
        int md = detect_mode((const unsigned int*)mask, lane);
        if (lane == 0) ((int*)sm)[SM_MODE] = md;
    }
    // Pn[n][k] = proj[k*32+n]  (B in col-major for wmma: column n has stride 520)
    for (int i = tid; i < Dq * Hq; i += 256) {
        int k = i >> 5, n = i & 31;
        sm[SM_PN + n * XSTRIDE + k] = proj[i];
    }
    // Ht[k][h] = hid[h*32+k] with XOR chunk swizzle (proven R3 layout)
    for (int i = tid; i < Hq * Hq; i += 256) {
        int k = i >> 5, h = i & 31;
        int c = h >> 2;
        sm[SM_HT + k * 32 + (((c ^ ((k >> 2) & 7)) << 2) | (h & 3))] =
            hid[h * Hq + k];
    }
    const float4 ev4 = ((const float4*)ev)[hg];
    __syncthreads();

    const int mmode = ((const int*)sm)[SM_MODE];
    float* Xs = sm + SM_X;
    float* Ws = sm + SM_WS;

    const float* HtR0 = sm + SM_HT + (hg * 4 + 0) * 32;
    const float* HtR1 = HtR0 + 32;
    const float* HtR2 = HtR1 + 32;
    const float* HtR3 = HtR2 + 32;

    for (int s = blockIdx.x; s < NSLICE; s += gridDim.x) {
        const int t0 = s * 64;

        // ---- stage X: warp w stages rows w*8..w*8+7 (exact fp32) ----
#pragma unroll
        for (int tt = 0; tt < 8; ++tt) {
            const int r = wid * 8 + tt;
            const float4* src = (const float4*)(inp + (size_t)(t0 + r) * Dq);
            float* dstrow = Xs + r * XSTRIDE;
#pragma unroll
            for (int i2 = 0; i2 < 4; ++i2)
                *(float4*)(dstrow + i2 * 128 + lane * 4) = src[i2 * 32 + lane];
        }
        if (tid < 64)
            Ws[tid * WSTRIDE + 33] = mask_on(mask, mmode, t0 + tid) ? 1.0f : 0.0f;
        __syncthreads();

        // ---- projector GEMM: C[16,16] = X[mi] * P[:,ni], tf32 wmma ----
        {
            wmma::fragment<wmma::accumulator, 16, 16, 8, float> c;
            wmma::fill_fragment(c, 0.0f);
            const float* Abase = Xs + mi * 16 * XSTRIDE;
            const float* Bbase = sm + SM_PN + ni * 16 * XSTRIDE;
#pragma unroll 4
            for (int k = 0; k < 64; ++k) {
                wmma::fragment<wmma::matrix_a, 16, 16, 8,
                               wmma::precision::tf32, wmma::row_major> a;
                wmma::fragment<wmma::matrix_b, 16, 16, 8,
                               wmma::precision::tf32, wmma::col_major> bf;
                wmma::load_matrix_sync(a, Abase + k * 8, XSTRIDE);
                wmma::load_matrix_sync(bf, Bbase + k * 8, XSTRIDE);
#pragma unroll
                for (int t = 0; t < a.num_elements; ++t)
                    a.x[t] = wmma::__float_to_tf32(a.x[t]);
#pragma unroll
                for (int t = 0; t < bf.num_elements; ++t)
                    bf.x[t] = wmma::__float_to_tf32(bf.x[t]);
                wmma::mma_sync(c, a, bf, c);
            }
            // sigmoid in-register, then store w0
#pragma unroll
            for (int t = 0; t < c.num_elements; ++t)
                c.x[t] = sigmoidf(c.x[t] * RSCALE);
            wmma::store_matrix_sync(Ws + (mi * 16) * WSTRIDE + ni * 16, c,
                                    WSTRIDE, wmma::mem_row_major);
        }
        __syncthreads();

        // ---- hidden layer (fp32 f32x2): warp handles tokens wid*8.. ----
        unsigned long long acc1[2][4];
#pragma unroll
        for (int a2 = 0; a2 < 2; ++a2)
#pragma unroll
            for (int c2 = 0; c2 < 4; ++c2) acc1[a2][c2] = 0ull;

        const float* w0a = Ws + (wid * 8 + 2 * tg) * WSTRIDE;
        const float* w0b = w0a + WSTRIDE;
#pragma unroll
        for (int c = 0; c < 8; ++c) {
            const int h0 = c << 2;
            const int po = ((c ^ hg) << 2);
            ulonglong2 wa = *(const ulonglong2*)(w0a + h0);
            ulonglong2 wb = *(const ulonglong2*)(w0b + h0);
            ulonglong2 q0 = *(const ulonglong2*)(HtR0 + po);
            ulonglong2 q1 = *(const ulonglong2*)(HtR1 + po);
            ulonglong2 q2 = *(const ulonglong2*)(HtR2 + po);
            ulonglong2 q3 = *(const ulonglong2*)(HtR3 + po);
            fma2(acc1[0][0], wa.x, q0.x); fma2(acc1[0][0], wa.y, q0.y);
            fma2(acc1[0][1], wa.x, q1.x); fma2(acc1[0][1], wa.y, q1.y);
            fma2(acc1[0][2], wa.x, q2.x); fma2(acc1[0][2], wa.y, q2.y);
            fma2(acc1[0][3], wa.x, q3.x); fma2(acc1[0][3], wa.y, q3.y);
            fma2(acc1[1][0], wb.x, q0.x); fma2(acc1[1][0], wb.y, q0.y);
            fma2(acc1[1][1], wb.x, q1.x); fma2(acc1[1][1], wb.y, q1.y);
            fma2(acc1[1][2], wb.x, q2.x); fma2(acc1[1][2], wb.y, q2.y);
            fma2(acc1[1][3], wb.x, q3.x); fma2(acc1[1][3], wb.y, q3.y);
        }

        // ---- evaluator + final sigmoid + exp (mask gates wf) ----
#pragma unroll
        for (int tp = 0; tp < 2; ++tp) {
            float2 a0 = upk(acc1[tp][0]);
            float2 a1 = upk(acc1[tp][1]);
            float2 a2 = upk(acc1[tp][2]);
            float2 a3 = upk(acc1[tp][3]);
            float e = sigmoidf((a0.x + a0.y) * RSCALE) * ev4.x +
                      sigmoidf((a1.x + a1.y) * RSCALE) * ev4.y +
                      sigmoidf((a2.x + a2.y) * RSCALE) * ev4.z +
                      sigmoidf((a3.x + a3.y) * RSCALE) * ev4.w;
            e += __shfl_xor_sync(0xffffffffu, e, 1);
            e += __shfl_xor_sync(0xffffffffu, e, 2);
            e += __shfl_xor_sync(0xffffffffu, e, 4);
            float z = sigmoidf(e * RSCALE);
            const int trow = wid * 8 + 2 * tg + tp;
            float m = Ws[trow * WSTRIDE + 33];
            if (hg == 0)
                Ws[trow * WSTRIDE + 32] = (m != 0.0f) ? __expf(z) : 0.0f;
        }
        __syncwarp();

        // ---- epilogue: per-warp sum of wf * x (exact fp32) ----
        float accd[16];
#pragma unroll
        for (int j = 0; j < 16; ++j) accd[j] = 0.0f;
        float wfs = 0.0f;
#pragma unroll
        for (int tt = 0; tt < 8; ++tt) {
            float wf = Ws[(wid * 8 + tt) * WSTRIDE + 32];
            wfs += wf;
            const float* xr = Xs + (wid * 8 + tt) * XSTRIDE + lane;
#pragma unroll
            for (int j = 0; j < 16; ++j) accd[j] += wf * xr[j * 32];
        }
        __syncthreads();   // X reads done; overlay reduction on X region

        float* red = Xs;   // [8][512]
#pragma unroll
        for (int j = 0; j < 16; ++j)
            red[wid * 512 + j * 32 + lane] = accd[j];
        if (lane == 0) sm[SM_WFS + wid] = wfs;
        __syncthreads();

        for (int d = tid; d < 512; d += 256) {
            float sacc = 0.0f;
#pragma unroll
            for (int r = 0; r < 8; ++r) sacc += red[r * 512 + d];
            g_part[s][d] = sacc;
        }
        if (tid == 0) {
            float sw = 0.0f;
#pragma unroll
            for (int r = 0; r < 8; ++r) sw += sm[SM_WFS + r];
            g_wfs[s] = sw;
        }
        __syncthreads();   // red reads done before next slice restages X
    }
}

// ---------------- kernel: reduce slices + normalize ----------------
// 64 blocks x 256 threads; each block covers one batch half (single b).
__global__ void k_final(float* __restrict__ out) {
    __shared__ float s_bsum;
    const int i = blockIdx.x * 256 + threadIdx.x;   // 16384 outputs
    const int b = i >> 9;
    if (threadIdx.x == 0) {
        float sw = 0.0f;
#pragma unroll
        for (int k = 0; k < 32; ++k) sw += g_wfs[b * 32 + k];
        s_bsum = sw;
    }
    __syncthreads();
    const int d = i & 511;
    float acc = 0.0f;
#pragma unroll
    for (int k = 0; k < 32; ++k) acc += g_part[b * 32 + k][d];
    out[i] = acc / (s_bsum + 1e-12f);
}

// ---------------- launcher ----------------
extern "C" void kernel_launch(void* const* d_in, const int* in_sizes, int n_in,
                              void* d_out, int out_size) {
    const float* inp  = (const float*)d_in[0];
    const void*  mask = d_in[1];
    const float* proj = (const float*)d_in[2];
    const float* hid  = (const float*)d_in[3];
    const float* ev   = (const float*)d_in[4];
    float* out = (float*)d_out;

    cudaFuncSetAttribute(k_main, cudaFuncAttributeMaxDynamicSharedMemorySize,
                         SMEM_BYTES);

    k_main<<<152, 256, SMEM_BYTES>>>(inp, mask, proj, hid, ev);
    k_final<<<Bq * Dq / 256, 256>>>(out);
}

// round 6
// speedup vs baseline: 1.1113x; 1.1113x over previous
#include <cuda_runtime.h>
#include <cstdint>

// Problem constants
#define Bq 32
#define Sq 2048
#define Dq 512
#define Hq 32
#define NTOK (Bq * Sq)        // 65536
#define NT   512              // threads per block in k_main
#define GRID 152

// ---------------- shared layout (float offsets) ----------------
#define SM_MISC 0                 // [0]=ns,[1]=b0,[2]=b1
#define SM_HT   16                // 32 rows x 36        -> 1168
#define SM_WS   1168              // 32 rows x 40 (w0, 32=wf, 33=valid) -> 2448
#define SM_PT   2448              // Pt[h][512] XOR-swizzled -> 18832
#define SM_X0   18832             // X buf0: 32 x 516    -> 35344
#define SM_X1   35344             // X buf1: 32 x 516    -> 51856
#define SM_FLOATS 51856
#define SMEM_BYTES (SM_FLOATS * 4)   // 207424

#define RSCALE 0.17677669529663687f  // 1/sqrt(32)

// ---------------- scratch ----------------
__device__ int   g_count;
__device__ int   g_bcnt[256];
__device__ int   g_idx[NTOK];
__device__ float g_bsum[Bq];
__device__ float g_acc[Bq * Dq];

// ---------------- helpers ----------------
__device__ __forceinline__ void fma2(unsigned long long& d,
                                     unsigned long long a,
                                     unsigned long long b) {
    asm("fma.rn.f32x2 %0, %1, %2, %3;" : "=l"(d) : "l"(a), "l"(b), "l"(d));
}
__device__ __forceinline__ float2 upk(unsigned long long v) {
    float2 r;
    asm("mov.b64 {%0, %1}, %2;" : "=f"(r.x), "=f"(r.y) : "l"(v));
    return r;
}
__device__ __forceinline__ float sigmoidf(float v) {
    return 1.0f / (1.0f + __expf(-v));
}
__device__ __forceinline__ uint32_t smem_u32(const void* p) {
    uint32_t a;
    asm("{ .reg .u64 t; cvta.to.shared.u64 t, %1; cvt.u32.u64 %0, t; }"
        : "=r"(a) : "l"(p));
    return a;
}
__device__ __forceinline__ void cp16(uint32_t dst, const void* src) {
    asm volatile("cp.async.cg.shared.global [%0], [%1], 16;"
                 :: "r"(dst), "l"(src) : "memory");
}
#define CP_COMMIT() asm volatile("cp.async.commit_group;" ::: "memory")
#define CP_WAIT0()  asm volatile("cp.async.wait_group 0;" ::: "memory")

__device__ __forceinline__ bool mask_on(const void* mask, int mm, int t) {
    if (mm == 1) return ((const int*)mask)[t] != 0;
    if (mm == 2) return ((const float*)mask)[t] != 0.0f;
    return ((const unsigned char*)mask)[t] != 0;
}
__device__ __forceinline__ int detect_mode(const unsigned int* m, int lane) {
    bool ai = true, af = true;
#pragma unroll
    for (int k = 0; k < 8; ++k) {
        unsigned v = m[lane * 8 + k];
        ai &= (v <= 1u);
        af &= (v == 0u || v == 0x3F800000u);
    }
    unsigned bi = __ballot_sync(0xffffffffu, ai);
    unsigned bf = __ballot_sync(0xffffffffu, af);
    return (bi == 0xffffffffu) ? 1 : ((bf == 0xffffffffu) ? 2 : 0);
}

// -------------------- kernel 1: counts + zero accumulators ----------------
__global__ void k_count(const void* mask) {
    __shared__ int wcnt[8];
    __shared__ int s_mode;
    const int tid = threadIdx.x, bid = blockIdx.x;
    if (tid < 32) {
        int md = detect_mode((const unsigned int*)mask, tid);
        if (tid == 0) s_mode = md;
    }
    if (bid < 64) g_acc[bid * 256 + tid] = 0.0f;
    if (bid == 0 && tid < Bq) g_bsum[tid] = 0.0f;
    __syncthreads();
    bool on = mask_on(mask, s_mode, bid * 256 + tid);
    unsigned bal = __ballot_sync(0xffffffffu, on);
    if ((tid & 31) == 0) wcnt[tid >> 5] = __popc(bal);
    __syncthreads();
    if (tid == 0) {
        int s = 0;
#pragma unroll
        for (int w = 0; w < 8; ++w) s += wcnt[w];
        g_bcnt[bid] = s;
    }
}

// -------------------- kernel 2: ordered fill (scan folded in) -------------
__global__ void k_fill(const void* mask) {
    __shared__ int s_mode, s_boff, wbase[8];
    const int tid = threadIdx.x, lane = tid & 31, wid = tid >> 5;
    const int bid = blockIdx.x;
    if (wid == 0) {
        int md = detect_mode((const unsigned int*)mask, lane);
        int pre = 0, tot = 0;
#pragma unroll
        for (int j = 0; j < 8; ++j) {
            int idx = lane + 32 * j;
            int v = g_bcnt[idx];
            tot += v;
            if (idx < bid) pre += v;
        }
#pragma unroll
        for (int o = 16; o; o >>= 1) {
            pre += __shfl_xor_sync(0xffffffffu, pre, o);
            tot += __shfl_xor_sync(0xffffffffu, tot, o);
        }
        if (lane == 0) {
            s_mode = md;
            s_boff = pre;
            if (bid == 0) g_count = tot;
        }
    }
    __syncthreads();
    const int t = bid * 256 + tid;
    bool on = mask_on(mask, s_mode, t);
    unsigned bal = __ballot_sync(0xffffffffu, on);
    if (lane == 0) wbase[wid] = __popc(bal);
    __syncthreads();
    int wb = 0;
#pragma unroll
    for (int w = 0; w < 8; ++w) wb += (w < wid) ? wbase[w] : 0;
    if (on)
        g_idx[s_boff + wb + __popc(bal & ((1u << lane) - 1u))] = t;
}

// -------------------- prefetch one 32-token slice via cp.async ------------
__device__ __forceinline__ void prefetch_slice(uint32_t xbase, const float* inp,
                                               int s, int count,
                                               int wid, int lane) {
    const int r  = 2 * wid + (lane >> 4);
    const int hl = lane & 15;
    int slot = s * 32 + r;
    int tok  = g_idx[min(slot, count - 1)];
    const char* src = (const char*)(inp + (size_t)tok * Dq) + hl * 16;
    uint32_t dst = xbase + (uint32_t)r * 2064u + (uint32_t)hl * 16u;
#pragma unroll
    for (int j = 0; j < 8; ++j)
        cp16(dst + j * 256u, src + j * 256);
}

// -------------------- kernel 3: persistent main ----------------------------
// 512 threads. GEMM phase: warps 0-3 x 8 tokens (proven FFMA2 inner loop).
// Hidden/evaluator: 16 warps x 2 tokens. Epilogue: 512 threads = 512 d.
__global__ void __launch_bounds__(NT) k_main(const float* __restrict__ inp,
                                             const float* __restrict__ proj,
                                             const float* __restrict__ hid,
                                             const float* __restrict__ ev) {
    extern __shared__ float sm[];
    const int tid  = threadIdx.x;
    const int lane = tid & 31;
    const int wid  = tid >> 5;
    const int tg   = lane >> 3;   // GEMM token group (0..3)
    const int hg   = lane & 7;    // GEMM h group (0..7)

    const int count = g_count;
    const int nsl   = (count + 31) >> 5;

    // ---- stage Pt (XOR chunk swizzle, proven R3 layout) ----
    for (int i = tid; i < Dq * Hq; i += NT) {
        int h = i >> 9, d = i & 511;
        int c = d >> 2;
        sm[SM_PT + h * 512 + (((c ^ ((h >> 2) & 7)) << 2) | (d & 3))] =
            proj[d * Hq + h];
    }
    // ---- stage Ht rows (stride 36, no swizzle) ----
    for (int i = tid; i < Hq * Hq; i += NT) {
        int k = i >> 5, h = i & 31;
        sm[SM_HT + k * 36 + h] = hid[h * Hq + k];
    }
    const float2 ev2 = ((const float2*)ev)[lane & 15];

    const uint32_t smb = smem_u32(sm);
    const float* PtR0 = sm + SM_PT + (hg * 4 + 0) * 512;
    const float* PtR1 = PtR0 + 512;
    const float* PtR2 = PtR1 + 512;
    const float* PtR3 = PtR2 + 512;

    int buf = 0;
    if (blockIdx.x < nsl)
        prefetch_slice(smb + SM_X0 * 4, inp, blockIdx.x, count, wid, lane);
    CP_COMMIT();
    __syncthreads();

    for (int s = blockIdx.x; s < nsl; s += gridDim.x) {
        float* Xs = sm + (buf ? SM_X1 : SM_X0);
        CP_WAIT0();
        __syncthreads();

        // ---- slice metadata (warp 0): valid flags, batch split ----
        if (tid < 32) {
            int slot = s * 32 + tid;
            int val  = slot < count;
            int tok  = g_idx[min(slot, count - 1)];
            int b    = tok >> 11;
            sm[SM_WS + tid * 40 + 33] = val ? 1.0f : 0.0f;
            int bA = __shfl_sync(0xffffffffu, b, 0);
            int bB = __shfl_sync(0xffffffffu, b, 31);
            unsigned mb = __ballot_sync(0xffffffffu, b == bA);
            if (tid == 0) {
                ((int*)sm)[SM_MISC + 0] = __popc(mb);   // sorted -> prefix len
                ((int*)sm)[SM_MISC + 1] = bA;
                ((int*)sm)[SM_MISC + 2] = bB;
            }
        }

        // ---- prefetch next slice into other buffer ----
        int s2 = s + gridDim.x;
        if (s2 < nsl)
            prefetch_slice(smb + (buf ? SM_X0 : SM_X1) * 4, inp, s2, count,
                           wid, lane);
        CP_COMMIT();

        // ---- GEMM phase: warps 0-3, 8 tokens each ----
        if (wid < 4) {
            unsigned long long acc[2][4];
#pragma unroll
            for (int a = 0; a < 2; ++a)
#pragma unroll
                for (int b2 = 0; b2 < 4; ++b2) acc[a][b2] = 0ull;

            const float* x0 = Xs + (wid * 8 + 2 * tg) * 516;
            const float* x1 = x0 + 516;
#pragma unroll 4
            for (int c = 0; c < 128; ++c) {
                const int d0 = c << 2;
                const int po = ((c ^ hg) << 2);
                ulonglong2 xa = *(const ulonglong2*)(x0 + d0);
                ulonglong2 xb = *(const ulonglong2*)(x1 + d0);
                ulonglong2 p0 = *(const ulonglong2*)(PtR0 + po);
                ulonglong2 p1 = *(const ulonglong2*)(PtR1 + po);
                ulonglong2 p2 = *(const ulonglong2*)(PtR2 + po);
                ulonglong2 p3 = *(const ulonglong2*)(PtR3 + po);
                fma2(acc[0][0], xa.x, p0.x); fma2(acc[0][0], xa.y, p0.y);
                fma2(acc[0][1], xa.x, p1.x); fma2(acc[0][1], xa.y, p1.y);
                fma2(acc[0][2], xa.x, p2.x); fma2(acc[0][2], xa.y, p2.y);
                fma2(acc[0][3], xa.x, p3.x); fma2(acc[0][3], xa.y, p3.y);
                fma2(acc[1][0], xb.x, p0.x); fma2(acc[1][0], xb.y, p0.y);
                fma2(acc[1][1], xb.x, p1.x); fma2(acc[1][1], xb.y, p1.y);
                fma2(acc[1][2], xb.x, p2.x); fma2(acc[1][2], xb.y, p2.y);
                fma2(acc[1][3], xb.x, p3.x); fma2(acc[1][3], xb.y, p3.y);
            }
#pragma unroll
            for (int tp = 0; tp < 2; ++tp) {
                float4 w4;
                float2 a0 = upk(acc[tp][0]); w4.x = sigmoidf((a0.x + a0.y) * RSCALE);
                float2 a1 = upk(acc[tp][1]); w4.y = sigmoidf((a1.x + a1.y) * RSCALE);
                float2 a2 = upk(acc[tp][2]); w4.z = sigmoidf((a2.x + a2.y) * RSCALE);
                float2 a3 = upk(acc[tp][3]); w4.w = sigmoidf((a3.x + a3.y) * RSCALE);
                *(float4*)(sm + SM_WS + (wid * 8 + 2 * tg + tp) * 40 + hg * 4) = w4;
            }
        }
        __syncthreads();

        // ---- hidden + evaluator: 16 warps x 2 tokens ----
        {
            const int tp   = lane >> 4;
            const int hl   = lane & 15;
            const int trow = wid * 2 + tp;
            const float* w0r = sm + SM_WS + trow * 40;
            const float* HtA = sm + SM_HT + (2 * hl) * 36;
            const float* HtB = HtA + 36;
            unsigned long long a0 = 0ull, a1 = 0ull;
#pragma unroll
            for (int c = 0; c < 8; ++c) {
                ulonglong2 wv = *(const ulonglong2*)(w0r + (c << 2));
                ulonglong2 q0 = *(const ulonglong2*)(HtA + (c << 2));
                ulonglong2 q1 = *(const ulonglong2*)(HtB + (c << 2));
                fma2(a0, wv.x, q0.x); fma2(a0, wv.y, q0.y);
                fma2(a1, wv.x, q1.x); fma2(a1, wv.y, q1.y);
            }
            float2 r0 = upk(a0), r1 = upk(a1);
            float e = sigmoidf((r0.x + r0.y) * RSCALE) * ev2.x +
                      sigmoidf((r1.x + r1.y) * RSCALE) * ev2.y;
            e += __shfl_xor_sync(0xffffffffu, e, 1);
            e += __shfl_xor_sync(0xffffffffu, e, 2);
            e += __shfl_xor_sync(0xffffffffu, e, 4);
            e += __shfl_xor_sync(0xffffffffu, e, 8);
            float z = sigmoidf(e * RSCALE);
            float val = sm[SM_WS + trow * 40 + 33];
            if (hl == 0)
                sm[SM_WS + trow * 40 + 32] = (val != 0.0f) ? __expf(z) : 0.0f;
        }
        __syncthreads();

        // ---- epilogue: thread d = tid, split loop at batch boundary ----
        {
            const int ns = ((const int*)sm)[SM_MISC + 0];
            const int b0 = ((const int*)sm)[SM_MISC + 1];
            const int b1 = ((const int*)sm)[SM_MISC + 2];
            float a0 = 0.0f, a1 = 0.0f;
            const float* Wsr = sm + SM_WS;
            for (int t = 0; t < ns; ++t)
                a0 += Wsr[t * 40 + 32] * Xs[t * 516 + tid];
            for (int t = ns; t < 32; ++t)
                a1 += Wsr[t * 40 + 32] * Xs[t * 516 + tid];
            atomicAdd(&g_acc[b0 * Dq + tid], a0);
            if (b1 != b0) atomicAdd(&g_acc[b1 * Dq + tid], a1);
            if (tid < 32) {
                float wf = Wsr[tid * 40 + 32];
                float wa = (tid < ns) ? wf : 0.0f;
                float wb = wf - wa;
#pragma unroll
                for (int o = 16; o; o >>= 1) {
                    wa += __shfl_xor_sync(0xffffffffu, wa, o);
                    wb += __shfl_xor_sync(0xffffffffu, wb, o);
                }
                if (tid == 0) {
                    atomicAdd(&g_bsum[b0], wa);
                    if (b1 != b0) atomicAdd(&g_bsum[b1], wb);
                }
            }
        }
        __syncthreads();
        buf ^= 1;
    }
}

// -------------------- kernel 4: normalize ----------------------------------
__global__ void k_final(float* __restrict__ out) {
    int i = blockIdx.x * 256 + threadIdx.x;
    out[i] = g_acc[i] / (g_bsum[i >> 9] + 1e-12f);
}

// -------------------- launcher --------------------
extern "C" void kernel_launch(void* const* d_in, const int* in_sizes, int n_in,
                              void* d_out, int out_size) {
    const float* inp  = (const float*)d_in[0];
    const void*  mask = d_in[1];
    const float* proj = (const float*)d_in[2];
    const float* hid  = (const float*)d_in[3];
    const float* ev   = (const float*)d_in[4];
    float* out = (float*)d_out;

    cudaFuncSetAttribute(k_main, cudaFuncAttributeMaxDynamicSharedMemorySize,
                         SMEM_BYTES);

    k_count<<<256, 256>>>(mask);
    k_fill<<<256, 256>>>(mask);
    k_main<<<GRID, NT, SMEM_BYTES>>>(inp, proj, hid, ev);
    k_final<<<Bq * Dq / 256, 256>>>(out);
}

// round 7
// speedup vs baseline: 1.4224x; 1.2799x over previous
#include <cuda_runtime.h>
#include <cstdint>

// Problem constants
#define Bq 32
#define Sq 2048
#define Dq 512
#define Hq 32
#define NTOK (Bq * Sq)        // 65536
#define GRID 152
#define NT   256

// ---------------- shared layout (float offsets) ----------------
#define SM_HT   0                 // Ht swizzled 32x32        -> 1024
#define SM_WS   1024              // Ws[64][36] (w0, 32=wf)   -> 3328
#define SM_TBL  3328              // ints: P[33] + scnt[32]   -> 3408 (padded)
#define SM_PT   3408              // Pt[32][512] XOR-swizzled -> 19792
#define SM_X    19792             // X[64][516]               -> 52816
#define SM_FLOATS 52816
#define SMEM_BYTES (SM_FLOATS * 4)   // 211264

#define RSCALE 0.17677669529663687f  // 1/sqrt(32)

// ---------------- scratch ----------------
__device__ int      g_bcnt[256];      // per-256-token-chunk counts
__device__ int      g_cnt[Bq];        // per-batch counts
__device__ int      g_idx[NTOK];      // per-batch compacted indices
__device__ float    g_bsum[Bq];
__device__ float    g_acc[Bq * Dq];
__device__ unsigned g_bar1 = 0u;      // monotonic grid-barrier counters
__device__ unsigned g_bar2 = 0u;

// ---------------- helpers ----------------
__device__ __forceinline__ void fma2(unsigned long long& d,
                                     unsigned long long a,
                                     unsigned long long b) {
    asm("fma.rn.f32x2 %0, %1, %2, %3;" : "=l"(d) : "l"(a), "l"(b), "l"(d));
}
__device__ __forceinline__ float2 upk(unsigned long long v) {
    float2 r;
    asm("mov.b64 {%0, %1}, %2;" : "=f"(r.x), "=f"(r.y) : "l"(v));
    return r;
}
__device__ __forceinline__ float sigmoidf(float v) {
    return 1.0f / (1.0f + __expf(-v));
}
__device__ __forceinline__ uint32_t smem_u32(const void* p) {
    uint32_t a;
    asm("{ .reg .u64 t; cvta.to.shared.u64 t, %1; cvt.u32.u64 %0, t; }"
        : "=r"(a) : "l"(p));
    return a;
}
__device__ __forceinline__ void cp16(uint32_t dst, const void* src) {
    asm volatile("cp.async.cg.shared.global [%0], [%1], 16;"
                 :: "r"(dst), "l"(src) : "memory");
}
#define CP_COMMIT() asm volatile("cp.async.commit_group;" ::: "memory")
#define CP_WAIT0()  asm volatile("cp.async.wait_group 0;" ::: "memory")

__device__ __forceinline__ bool mask_on(const void* mask, int mm, int t) {
    if (mm == 1) return ((const int*)mask)[t] != 0;
    if (mm == 2) return ((const float*)mask)[t] != 0.0f;
    return ((const unsigned char*)mask)[t] != 0;
}
__device__ __forceinline__ int detect_mode(const unsigned int* m, int lane) {
    bool ai = true, af = true;
#pragma unroll
    for (int k = 0; k < 8; ++k) {
        unsigned v = m[lane * 8 + k];
        ai &= (v <= 1u);
        af &= (v == 0u || v == 0x3F800000u);
    }
    unsigned bi = __ballot_sync(0xffffffffu, ai);
    unsigned bf = __ballot_sync(0xffffffffu, af);
    return (bi == 0xffffffffu) ? 1 : ((bf == 0xffffffffu) ? 2 : 0);
}

// Monotonic grid barrier: all nb blocks must be co-resident (they are:
// k_prep 256 small blocks; k_main 152 blocks at 1/SM). Counter never resets;
// target derived from own arrival index, so it works across graph replays.
__device__ __forceinline__ void grid_barrier(unsigned* bar, unsigned nb) {
    __syncthreads();
    if (threadIdx.x == 0) {
        __threadfence();
        unsigned r = atomicAdd(bar, 1u);
        unsigned target = (r / nb + 1u) * nb;
        while (*((volatile unsigned*)bar) < target) {}
    }
    __syncthreads();
}

// -------------------- kernel 1: one-pass ordered per-batch compaction ------
// 256 blocks x 256 threads; block bid covers tokens [bid*256, bid*256+256)
// which lie inside batch b = bid>>3.
__global__ void k_prep(const void* mask) {
    __shared__ int wcnt[8];
    __shared__ int s_mode;
    const int tid = threadIdx.x, bid = blockIdx.x;
    const int lane = tid & 31, wid = tid >> 5;

    if (wid == 0) {
        int md = detect_mode((const unsigned int*)mask, lane);
        if (lane == 0) s_mode = md;
    }
    const int g = bid * 256 + tid;
    if (bid < 64) g_acc[g] = 0.0f;
    if (g < Bq) g_bsum[g] = 0.0f;
    __syncthreads();

    const int mm = s_mode;
    const bool on = mask_on(mask, mm, g);
    const unsigned bal = __ballot_sync(0xffffffffu, on);
    if (lane == 0) wcnt[wid] = __popc(bal);
    __syncthreads();

    int btot = 0, wbase = 0;
#pragma unroll
    for (int w = 0; w < 8; ++w) {
        if (w < wid) wbase += wcnt[w];
        btot += wcnt[w];
    }
    if (tid == 0) g_bcnt[bid] = btot;

    grid_barrier(&g_bar1, 256);

    const int b = bid >> 3;
    int off = 0, cnt = 0;
#pragma unroll
    for (int j = 0; j < 8; ++j) {
        int idx = b * 8 + j;
        int v = __ldcg(&g_bcnt[idx]);
        cnt += v;
        if (idx < bid) off += v;
    }
    if (tid == 0) g_cnt[b] = cnt;
    if (on)
        g_idx[b * 2048 + off + wbase + __popc(bal & ((1u << lane) - 1u))] = g;
}

// -------------------- kernel 2: persistent main + fused final --------------
// 152 blocks x 256 threads; R3 structure: 8 warps, 8 tokens each, identical
// full pipeline per warp. Slices are single-batch by construction.
__global__ void __launch_bounds__(NT) k_main(const float* __restrict__ inp,
                                             const float* __restrict__ proj,
                                             const float* __restrict__ hid,
                                             const float* __restrict__ ev,
                                             float* __restrict__ out) {
    extern __shared__ float sm[];
    const int tid  = threadIdx.x;
    const int lane = tid & 31;
    const int wid  = tid >> 5;
    const int tg   = lane >> 3;
    const int hg   = lane & 7;

    // ---- stage Pt (XOR chunk swizzle, proven R3 layout) ----
    for (int i = tid; i < Dq * Hq; i += NT) {
        int h = i >> 9, d = i & 511;
        int c = d >> 2;
        sm[SM_PT + h * 512 + (((c ^ ((h >> 2) & 7)) << 2) | (d & 3))] =
            proj[d * Hq + h];
    }
    // ---- stage Ht (XOR chunk swizzle, stride 32, proven R3 layout) ----
    for (int i = tid; i < Hq * Hq; i += NT) {
        int k = i >> 5, h = i & 31;
        int c = h >> 2;
        sm[SM_HT + k * 32 + (((c ^ ((k >> 2) & 7)) << 2) | (h & 3))] =
            hid[h * Hq + k];
    }
    const float4 ev4 = ((const float4*)ev)[hg];

    // ---- slice table: P[33] inclusive prefix of per-batch slice counts ----
    int* P    = (int*)(sm + SM_TBL);       // 33 ints
    int* scnt = (int*)(sm + SM_TBL) + 33;  // 32 ints
    if (tid < 32) {
        int c = g_cnt[tid];
        scnt[tid] = c;
        int x = (c + 63) >> 6;
#pragma unroll
        for (int o = 1; o < 32; o <<= 1) {
            int y = __shfl_up_sync(0xffffffffu, x, o);
            if (lane >= o) x += y;
        }
        P[tid + 1] = x;
        if (tid == 0) P[0] = 0;
    }
    __syncthreads();
    const int NS = P[32];

    const uint32_t smb = smem_u32(sm);
    float* Xwarp = sm + SM_X + wid * (8 * 516);
    float* Wwarp = sm + SM_WS + wid * (8 * 36);
    const uint32_t xw_u32 = smb + (SM_X + wid * (8 * 516)) * 4u;

    const float* PtR0 = sm + SM_PT + (hg * 4 + 0) * 512;
    const float* PtR1 = PtR0 + 512;
    const float* PtR2 = PtR1 + 512;
    const float* PtR3 = PtR2 + 512;
    const float* HtR0 = sm + SM_HT + (hg * 4 + 0) * 32;
    const float* HtR1 = HtR0 + 32;
    const float* HtR2 = HtR1 + 32;
    const float* HtR3 = HtR2 + 32;

    for (int s = blockIdx.x; s < NS; s += GRID) {
        // ---- map slice -> (batch, local slice) ----
        int b = 0;
        while (s >= P[b + 1]) ++b;
        const int sl  = s - P[b];
        const int cnt = scnt[b];

        // ---- stage 8 token rows via cp.async (lane<8 holds indices) ----
        {
            int jr = sl * 64 + wid * 8 + (lane & 7);
            int myidx = g_idx[b * 2048 + min(jr, cnt - 1)];
#pragma unroll
            for (int tt = 0; tt < 8; ++tt) {
                int tok = __shfl_sync(0xffffffffu, myidx, tt);
                const char* src = (const char*)(inp + (size_t)tok * Dq) + lane * 16;
                uint32_t dst = xw_u32 + (uint32_t)tt * 2064u + (uint32_t)lane * 16u;
#pragma unroll
                for (int j = 0; j < 4; ++j)
                    cp16(dst + j * 512u, src + j * 512);
            }
            CP_COMMIT();
            CP_WAIT0();
            __syncwarp();
        }

        // ---- projector GEMM (R3 proven loop): 2 tokens x 4 h per lane ----
        unsigned long long acc[2][4];
#pragma unroll
        for (int a = 0; a < 2; ++a)
#pragma unroll
            for (int b2 = 0; b2 < 4; ++b2) acc[a][b2] = 0ull;

        const float* x0 = Xwarp + 2 * tg * 516;
        const float* x1 = x0 + 516;
#pragma unroll 4
        for (int c = 0; c < 128; ++c) {
            const int d0 = c << 2;
            const int po = ((c ^ hg) << 2);
            ulonglong2 xa = *(const ulonglong2*)(x0 + d0);
            ulonglong2 xb = *(const ulonglong2*)(x1 + d0);
            ulonglong2 p0 = *(const ulonglong2*)(PtR0 + po);
            ulonglong2 p1 = *(const ulonglong2*)(PtR1 + po);
            ulonglong2 p2 = *(const ulonglong2*)(PtR2 + po);
            ulonglong2 p3 = *(const ulonglong2*)(PtR3 + po);
            fma2(acc[0][0], xa.x, p0.x); fma2(acc[0][0], xa.y, p0.y);
            fma2(acc[0][1], xa.x, p1.x); fma2(acc[0][1], xa.y, p1.y);
            fma2(acc[0][2], xa.x, p2.x); fma2(acc[0][2], xa.y, p2.y);
            fma2(acc[0][3], xa.x, p3.x); fma2(acc[0][3], xa.y, p3.y);
            fma2(acc[1][0], xb.x, p0.x); fma2(acc[1][0], xb.y, p0.y);
            fma2(acc[1][1], xb.x, p1.x); fma2(acc[1][1], xb.y, p1.y);
            fma2(acc[1][2], xb.x, p2.x); fma2(acc[1][2], xb.y, p2.y);
            fma2(acc[1][3], xb.x, p3.x); fma2(acc[1][3], xb.y, p3.y);
        }

        // ---- sigmoid -> w0 rows ----
#pragma unroll
        for (int tp = 0; tp < 2; ++tp) {
            float4 w4;
            float2 a0 = upk(acc[tp][0]); w4.x = sigmoidf((a0.x + a0.y) * RSCALE);
            float2 a1 = upk(acc[tp][1]); w4.y = sigmoidf((a1.x + a1.y) * RSCALE);
            float2 a2 = upk(acc[tp][2]); w4.z = sigmoidf((a2.x + a2.y) * RSCALE);
            float2 a3 = upk(acc[tp][3]); w4.w = sigmoidf((a3.x + a3.y) * RSCALE);
            *(float4*)(Wwarp + (2 * tg + tp) * 36 + hg * 4) = w4;
        }
        __syncwarp();

        // ---- hidden layer (R3 proven loop) ----
        unsigned long long acc1[2][4];
#pragma unroll
        for (int a = 0; a < 2; ++a)
#pragma unroll
            for (int b2 = 0; b2 < 4; ++b2) acc1[a][b2] = 0ull;

        const float* w0a = Wwarp + 2 * tg * 36;
        const float* w0b = w0a + 36;
#pragma unroll
        for (int c = 0; c < 8; ++c) {
            const int h0 = c << 2;
            const int po = ((c ^ hg) << 2);
            ulonglong2 wa = *(const ulonglong2*)(w0a + h0);
            ulonglong2 wb = *(const ulonglong2*)(w0b + h0);
            ulonglong2 q0 = *(const ulonglong2*)(HtR0 + po);
            ulonglong2 q1 = *(const ulonglong2*)(HtR1 + po);
            ulonglong2 q2 = *(const ulonglong2*)(HtR2 + po);
            ulonglong2 q3 = *(const ulonglong2*)(HtR3 + po);
            fma2(acc1[0][0], wa.x, q0.x); fma2(acc1[0][0], wa.y, q0.y);
            fma2(acc1[0][1], wa.x, q1.x); fma2(acc1[0][1], wa.y, q1.y);
            fma2(acc1[0][2], wa.x, q2.x); fma2(acc1[0][2], wa.y, q2.y);
            fma2(acc1[0][3], wa.x, q3.x); fma2(acc1[0][3], wa.y, q3.y);
            fma2(acc1[1][0], wb.x, q0.x); fma2(acc1[1][0], wb.y, q0.y);
            fma2(acc1[1][1], wb.x, q1.x); fma2(acc1[1][1], wb.y, q1.y);
            fma2(acc1[1][2], wb.x, q2.x); fma2(acc1[1][2], wb.y, q2.y);
            fma2(acc1[1][3], wb.x, q3.x); fma2(acc1[1][3], wb.y, q3.y);
        }

        // ---- evaluator + final sigmoid + exp; validity gates wf ----
#pragma unroll
        for (int tp = 0; tp < 2; ++tp) {
            float2 a0 = upk(acc1[tp][0]);
            float2 a1 = upk(acc1[tp][1]);
            float2 a2 = upk(acc1[tp][2]);
            float2 a3 = upk(acc1[tp][3]);
            float e = sigmoidf((a0.x + a0.y) * RSCALE) * ev4.x +
                      sigmoidf((a1.x + a1.y) * RSCALE) * ev4.y +
                      sigmoidf((a2.x + a2.y) * RSCALE) * ev4.z +
                      sigmoidf((a3.x + a3.y) * RSCALE) * ev4.w;
            e += __shfl_xor_sync(0xffffffffu, e, 1);
            e += __shfl_xor_sync(0xffffffffu, e, 2);
            e += __shfl_xor_sync(0xffffffffu, e, 4);
            float z = sigmoidf(e * RSCALE);
            const int trow = 2 * tg + tp;
            bool valid = (sl * 64 + wid * 8 + trow) < cnt;
            if (hg == 0)
                Wwarp[trow * 36 + 32] = valid ? __expf(z) : 0.0f;
        }
        __syncwarp();

        // ---- epilogue: per-warp wf*x over its 8 tokens (single batch) ----
        float accd[16];
#pragma unroll
        for (int j = 0; j < 16; ++j) accd[j] = 0.0f;
        float wfs = 0.0f;
#pragma unroll
        for (int tt = 0; tt < 8; ++tt) {
            float wf = Wwarp[tt * 36 + 32];
            wfs += wf;
            const float* xr = Xwarp + tt * 516 + lane;
#pragma unroll
            for (int j = 0; j < 16; ++j) accd[j] += wf * xr[j * 32];
        }
        __syncthreads();   // all X reads done; overlay reduction on X region

        float* red = sm + SM_X;   // [8][512] + wfs[8]
#pragma unroll
        for (int j = 0; j < 16; ++j)
            red[wid * 512 + j * 32 + lane] = accd[j];
        if (lane == 0) red[8 * 512 + wid] = wfs;
        __syncthreads();

#pragma unroll
        for (int d = tid; d < 512; d += NT) {
            float sacc = 0.0f;
#pragma unroll
            for (int r = 0; r < 8; ++r) sacc += red[r * 512 + d];
            atomicAdd(&g_acc[b * Dq + d], sacc);
        }
        if (tid == 0) {
            float sw = 0.0f;
#pragma unroll
            for (int r = 0; r < 8; ++r) sw += red[8 * 512 + r];
            atomicAdd(&g_bsum[b], sw);
        }
        __syncthreads();   // red reads done before next slice restages X
    }

    // ---- fused final: grid barrier, then normalize ----
    grid_barrier(&g_bar2, GRID);
    const int g = blockIdx.x * NT + tid;   // 38912 >= 16384
    if (g < Bq * Dq)
        out[g] = __ldcg(&g_acc[g]) / (__ldcg(&g_bsum[g >> 9]) + 1e-12f);
}

// -------------------- launcher --------------------
extern "C" void kernel_launch(void* const* d_in, const int* in_sizes, int n_in,
                              void* d_out, int out_size) {
    const float* inp  = (const float*)d_in[0];
    const void*  mask = d_in[1];
    const float* proj = (const float*)d_in[2];
    const float* hid  = (const float*)d_in[3];
    const float* ev   = (const float*)d_in[4];
    float* out = (float*)d_out;

    cudaFuncSetAttribute(k_main, cudaFuncAttributeMaxDynamicSharedMemorySize,
                         SMEM_BYTES);

    k_prep<<<256, 256>>>(mask);
    k_main<<<GRID, NT, SMEM_BYTES>>>(inp, proj, hid, ev, out);
}

// round 8
// speedup vs baseline: 1.9573x; 1.3761x over previous
#include <cuda_runtime.h>
#include <cuda_bf16.h>
#include <mma.h>
#include <cstdint>

using namespace nvcuda;

// Problem constants
#define Bq 32
#define Sq 2048
#define Dq 512
#define Hq 32
#define NTOK (Bq * Sq)        // 65536
#define GRID 152
#define NT   256

// ---------------- shared layout (float offsets) ----------------
#define XB_STRIDE 520             // bf16 row stride (1040B: 16B-bank rotation)
#define WS_STRIDE 40
#define SM_HT    0                // Ht swizzled 32x32          -> 1024
#define SM_TBL   1024             // ints P[33]+scnt[32] pad    -> 1104
#define SM_WS    1104             // Ws[64][40] (w0, col32=wf)  -> 3664
#define SM_X16   3664             // X bf16 [64][520] = 16640 f -> 20304
#define SM_PT16  20304            // P bf16 [32][520] = 8320 f  -> 28624
#define SM_FLOATS 28624
#define SMEM_BYTES (SM_FLOATS * 4)   // 114496

#define RSCALE 0.17677669529663687f  // 1/sqrt(32)

// ---------------- scratch ----------------
__device__ int      g_bcnt[256];
__device__ int      g_cnt[Bq];
__device__ int      g_idx[NTOK];
__device__ float    g_bsum[Bq];
__device__ float    g_acc[Bq * Dq];
__device__ unsigned g_bar1 = 0u;
__device__ unsigned g_bar2 = 0u;

// ---------------- helpers ----------------
__device__ __forceinline__ void fma2(unsigned long long& d,
                                     unsigned long long a,
                                     unsigned long long b) {
    asm("fma.rn.f32x2 %0, %1, %2, %3;" : "=l"(d) : "l"(a), "l"(b), "l"(d));
}
__device__ __forceinline__ float2 upk(unsigned long long v) {
    float2 r;
    asm("mov.b64 {%0, %1}, %2;" : "=f"(r.x), "=f"(r.y) : "l"(v));
    return r;
}
__device__ __forceinline__ float sigmoidf(float v) {
    return 1.0f / (1.0f + __expf(-v));
}
__device__ __forceinline__ bool mask_on(const void* mask, int mm, int t) {
    if (mm == 1) return ((const int*)mask)[t] != 0;
    if (mm == 2) return ((const float*)mask)[t] != 0.0f;
    return ((const unsigned char*)mask)[t] != 0;
}
__device__ __forceinline__ int detect_mode(const unsigned int* m, int lane) {
    bool ai = true, af = true;
#pragma unroll
    for (int k = 0; k < 8; ++k) {
        unsigned v = m[lane * 8 + k];
        ai &= (v <= 1u);
        af &= (v == 0u || v == 0x3F800000u);
    }
    unsigned bi = __ballot_sync(0xffffffffu, ai);
    unsigned bf = __ballot_sync(0xffffffffu, af);
    return (bi == 0xffffffffu) ? 1 : ((bf == 0xffffffffu) ? 2 : 0);
}

// Monotonic grid barrier (all nb blocks co-resident; counter never resets).
__device__ __forceinline__ void grid_barrier(unsigned* bar, unsigned nb) {
    __syncthreads();
    if (threadIdx.x == 0) {
        __threadfence();
        unsigned r = atomicAdd(bar, 1u);
        unsigned target = (r / nb + 1u) * nb;
        while (*((volatile unsigned*)bar) < target) {}
    }
    __syncthreads();
}

// -------------------- kernel 1: one-pass ordered per-batch compaction ------
__global__ void k_prep(const void* mask) {
    __shared__ int wcnt[8];
    __shared__ int s_mode;
    const int tid = threadIdx.x, bid = blockIdx.x;
    const int lane = tid & 31, wid = tid >> 5;

    if (wid == 0) {
        int md = detect_mode((const unsigned int*)mask, lane);
        if (lane == 0) s_mode = md;
    }
    const int g = bid * 256 + tid;
    if (bid < 64) g_acc[g] = 0.0f;
    if (g < Bq) g_bsum[g] = 0.0f;
    __syncthreads();

    const bool on = mask_on(mask, s_mode, g);
    const unsigned bal = __ballot_sync(0xffffffffu, on);
    if (lane == 0) wcnt[wid] = __popc(bal);
    __syncthreads();

    int btot = 0, wbase = 0;
#pragma unroll
    for (int w = 0; w < 8; ++w) {
        if (w < wid) wbase += wcnt[w];
        btot += wcnt[w];
    }
    if (tid == 0) g_bcnt[bid] = btot;

    grid_barrier(&g_bar1, 256);

    const int b = bid >> 3;
    int off = 0, cnt = 0;
#pragma unroll
    for (int j = 0; j < 8; ++j) {
        int idx = b * 8 + j;
        int v = __ldcg(&g_bcnt[idx]);
        cnt += v;
        if (idx < bid) off += v;
    }
    if (tid == 0) g_cnt[b] = cnt;
    if (on)
        g_idx[b * 2048 + off + wbase + __popc(bal & ((1u << lane) - 1u))] = g;
}

// -------------------- kernel 2: persistent main + fused final --------------
__global__ void __launch_bounds__(NT) k_main(const float* __restrict__ inp,
                                             const float* __restrict__ proj,
                                             const float* __restrict__ hid,
                                             const float* __restrict__ ev,
                                             float* __restrict__ out) {
    extern __shared__ float sm[];
    const int tid  = threadIdx.x;
    const int lane = tid & 31;
    const int wid  = tid >> 5;
    const int tg   = lane >> 3;
    const int hg   = lane & 7;
    const int mi   = wid >> 1;   // wmma M-tile (token group of 16)
    const int ni   = wid & 1;    // wmma N-tile (h group of 16)

    __nv_bfloat16* Xb = (__nv_bfloat16*)(sm + SM_X16);
    __nv_bfloat16* Pb = (__nv_bfloat16*)(sm + SM_PT16);

    // ---- stage P as bf16: Pb[n][k] = proj[k*32+n] ----
    for (int i = tid; i < Dq * Hq; i += NT) {
        int k = i >> 5, n = i & 31;
        Pb[n * XB_STRIDE + k] = __float2bfloat16(proj[i]);
    }
    // ---- stage Ht (XOR chunk swizzle, proven R3 layout) ----
    for (int i = tid; i < Hq * Hq; i += NT) {
        int k = i >> 5, h = i & 31;
        int c = h >> 2;
        sm[SM_HT + k * 32 + (((c ^ ((k >> 2) & 7)) << 2) | (h & 3))] =
            hid[h * Hq + k];
    }
    const float4 ev4 = ((const float4*)ev)[hg];

    // ---- slice table: inclusive prefix of per-batch slice counts ----
    int* P    = (int*)(sm + SM_TBL);
    int* scnt = (int*)(sm + SM_TBL) + 33;
    if (tid < 32) {
        int c = g_cnt[tid];
        scnt[tid] = c;
        int x = (c + 63) >> 6;
#pragma unroll
        for (int o = 1; o < 32; o <<= 1) {
            int y = __shfl_up_sync(0xffffffffu, x, o);
            if (lane >= o) x += y;
        }
        P[tid + 1] = x;
        if (tid == 0) P[0] = 0;
    }
    __syncthreads();
    const int NS = P[32];

    float* Wwarp = sm + SM_WS + wid * (8 * WS_STRIDE);

    const float* HtR0 = sm + SM_HT + (hg * 4 + 0) * 32;
    const float* HtR1 = HtR0 + 32;
    const float* HtR2 = HtR1 + 32;
    const float* HtR3 = HtR2 + 32;

    for (int s = blockIdx.x; s < NS; s += GRID) {
        // ---- map slice -> (batch, local slice) ----
        int b = 0;
        while (s >= P[b + 1]) ++b;
        const int sl  = s - P[b];
        const int cnt = scnt[b];

        // ---- stage 8 token rows as bf16 (lane<8 holds indices) ----
        const int jr = sl * 64 + wid * 8 + (lane & 7);
        const int myidx = g_idx[b * 2048 + min(jr, cnt - 1)];
#pragma unroll
        for (int tt = 0; tt < 8; ++tt) {
            int tok = __shfl_sync(0xffffffffu, myidx, tt);
            const float4* src = (const float4*)(inp + (size_t)tok * Dq);
            __nv_bfloat16* drow = Xb + (wid * 8 + tt) * XB_STRIDE;
#pragma unroll
            for (int i2 = 0; i2 < 4; ++i2) {
                float4 v = src[i2 * 32 + lane];
                __nv_bfloat162 lo = __float22bfloat162_rn(make_float2(v.x, v.y));
                __nv_bfloat162 hi = __float22bfloat162_rn(make_float2(v.z, v.w));
                *(__nv_bfloat162*)(drow + i2 * 128 + lane * 4 + 0) = lo;
                *(__nv_bfloat162*)(drow + i2 * 128 + lane * 4 + 2) = hi;
            }
        }
        __syncthreads();

        // ---- projector GEMM: warp (mi,ni) -> Z tile [16 tok x 16 h] ----
        {
            wmma::fragment<wmma::accumulator, 16, 16, 16, float> c;
            wmma::fill_fragment(c, 0.0f);
            const __nv_bfloat16* Abase = Xb + mi * 16 * XB_STRIDE;
            const __nv_bfloat16* Bbase = Pb + ni * 16 * XB_STRIDE;
#pragma unroll 4
            for (int ks = 0; ks < 32; ++ks) {
                wmma::fragment<wmma::matrix_a, 16, 16, 16, __nv_bfloat16,
                               wmma::row_major> a;
                wmma::fragment<wmma::matrix_b, 16, 16, 16, __nv_bfloat16,
                               wmma::col_major> bf;
                wmma::load_matrix_sync(a, Abase + ks * 16, XB_STRIDE);
                wmma::load_matrix_sync(bf, Bbase + ks * 16, XB_STRIDE);
                wmma::mma_sync(c, a, bf, c);
            }
#pragma unroll
            for (int t = 0; t < c.num_elements; ++t)
                c.x[t] = sigmoidf(c.x[t] * RSCALE);
            wmma::store_matrix_sync(sm + SM_WS + (mi * 16) * WS_STRIDE + ni * 16,
                                    c, WS_STRIDE, wmma::mem_row_major);
        }
        __syncthreads();

        // ---- hidden layer (fp32 f32x2, R3 proven loop) ----
        unsigned long long acc1[2][4];
#pragma unroll
        for (int a = 0; a < 2; ++a)
#pragma unroll
            for (int b2 = 0; b2 < 4; ++b2) acc1[a][b2] = 0ull;

        const float* w0a = Wwarp + 2 * tg * WS_STRIDE;
        const float* w0b = w0a + WS_STRIDE;
#pragma unroll
        for (int c = 0; c < 8; ++c) {
            const int h0 = c << 2;
            const int po = ((c ^ hg) << 2);
            ulonglong2 wa = *(const ulonglong2*)(w0a + h0);
            ulonglong2 wb = *(const ulonglong2*)(w0b + h0);
            ulonglong2 q0 = *(const ulonglong2*)(HtR0 + po);
            ulonglong2 q1 = *(const ulonglong2*)(HtR1 + po);
            ulonglong2 q2 = *(const ulonglong2*)(HtR2 + po);
            ulonglong2 q3 = *(const ulonglong2*)(HtR3 + po);
            fma2(acc1[0][0], wa.x, q0.x); fma2(acc1[0][0], wa.y, q0.y);
            fma2(acc1[0][1], wa.x, q1.x); fma2(acc1[0][1], wa.y, q1.y);
            fma2(acc1[0][2], wa.x, q2.x); fma2(acc1[0][2], wa.y, q2.y);
            fma2(acc1[0][3], wa.x, q3.x); fma2(acc1[0][3], wa.y, q3.y);
            fma2(acc1[1][0], wb.x, q0.x); fma2(acc1[1][0], wb.y, q0.y);
            fma2(acc1[1][1], wb.x, q1.x); fma2(acc1[1][1], wb.y, q1.y);
            fma2(acc1[1][2], wb.x, q2.x); fma2(acc1[1][2], wb.y, q2.y);
            fma2(acc1[1][3], wb.x, q3.x); fma2(acc1[1][3], wb.y, q3.y);
        }

        // ---- evaluator + final sigmoid + exp; validity gates wf ----
#pragma unroll
        for (int tp = 0; tp < 2; ++tp) {
            float2 a0 = upk(acc1[tp][0]);
            float2 a1 = upk(acc1[tp][1]);
            float2 a2 = upk(acc1[tp][2]);
            float2 a3 = upk(acc1[tp][3]);
            float e = sigmoidf((a0.x + a0.y) * RSCALE) * ev4.x +
                      sigmoidf((a1.x + a1.y) * RSCALE) * ev4.y +
                      sigmoidf((a2.x + a2.y) * RSCALE) * ev4.z +
                      sigmoidf((a3.x + a3.y) * RSCALE) * ev4.w;
            e += __shfl_xor_sync(0xffffffffu, e, 1);
            e += __shfl_xor_sync(0xffffffffu, e, 2);
            e += __shfl_xor_sync(0xffffffffu, e, 4);
            float z = sigmoidf(e * RSCALE);
            const int trow = 2 * tg + tp;
            bool valid = (sl * 64 + wid * 8 + trow) < cnt;
            if (hg == 0)
                Wwarp[trow * WS_STRIDE + 32] = valid ? __expf(z) : 0.0f;
        }
        __syncwarp();

        // ---- epilogue: wf * x with x re-read fp32 from global (L1-hot) ----
        float accd[16];
#pragma unroll
        for (int j = 0; j < 16; ++j) accd[j] = 0.0f;
        float wfs = 0.0f;
#pragma unroll
        for (int tt = 0; tt < 8; ++tt) {
            float wf = Wwarp[tt * WS_STRIDE + 32];
            wfs += wf;
            int tok = __shfl_sync(0xffffffffu, myidx, tt);
            const float* xg = inp + (size_t)tok * Dq + lane;
            if (wf != 0.0f) {
#pragma unroll
                for (int j = 0; j < 16; ++j) accd[j] += wf * __ldg(xg + j * 32);
            }
        }
        __syncthreads();   // Ws/X16 reads done; overlay reduction on X16

        float* red = sm + SM_X16;   // [8][512] + wfs[8]
#pragma unroll
        for (int j = 0; j < 16; ++j)
            red[wid * 512 + j * 32 + lane] = accd[j];
        if (lane == 0) red[8 * 512 + wid] = wfs;
        __syncthreads();

#pragma unroll
        for (int d = tid; d < 512; d += NT) {
            float sacc = 0.0f;
#pragma unroll
            for (int r = 0; r < 8; ++r) sacc += red[r * 512 + d];
            atomicAdd(&g_acc[b * Dq + d], sacc);
        }
        if (tid == 0) {
            float sw = 0.0f;
#pragma unroll
            for (int r = 0; r < 8; ++r) sw += red[8 * 512 + r];
            atomicAdd(&g_bsum[b], sw);
        }
        __syncthreads();   // red reads done before next slice restages X16
    }

    // ---- fused final: grid barrier, then normalize ----
    grid_barrier(&g_bar2, GRID);
    const int g = blockIdx.x * NT + tid;
    if (g < Bq * Dq)
        out[g] = __ldcg(&g_acc[g]) / (__ldcg(&g_bsum[g >> 9]) + 1e-12f);
}

// -------------------- launcher --------------------
extern "C" void kernel_launch(void* const* d_in, const int* in_sizes, int n_in,
                              void* d_out, int out_size) {
    const float* inp  = (const float*)d_in[0];
    const void*  mask = d_in[1];
    const float* proj = (const float*)d_in[2];
    const float* hid  = (const float*)d_in[3];
    const float* ev   = (const float*)d_in[4];
    float* out = (float*)d_out;

    cudaFuncSetAttribute(k_main, cudaFuncAttributeMaxDynamicSharedMemorySize,
                         SMEM_BYTES);

    k_prep<<<256, 256>>>(mask);
    k_main<<<GRID, NT, SMEM_BYTES>>>(inp, proj, hid, ev, out);
}

// round 9
// speedup vs baseline: 2.0187x; 1.0314x over previous
#include <cuda_runtime.h>
#include <cuda_bf16.h>
#include <mma.h>
#include <cstdint>

using namespace nvcuda;

// Problem constants
#define Bq 32
#define Sq 2048
#define Dq 512
#define Hq 32
#define NTOK (Bq * Sq)        // 65536
#define GRID 152
#define NT   512              // 16 warps = 2 independent halves of 8

// ---------------- shared layout (float offsets) ----------------
#define XB_STRIDE 520             // bf16 row stride (1040B -> 16B bank rotation)
#define WS_STRIDE 40
#define SM_HT    0                // Ht swizzled 32x32              -> 1024
#define SM_TBL   1024             // ints P[33]+scnt[32], padded    -> 1104
#define SM_WS    1104             // Ws[2][64][40]                  -> 6224
#define SM_X16   6224             // X bf16 [2][64][520] (33280 f)  -> 39504
#define SM_PT16  39504            // P bf16 [32][520] (8320 f)      -> 47824
#define SM_FLOATS 47824
#define SMEM_BYTES (SM_FLOATS * 4)   // 191296

#define RSCALE 0.17677669529663687f  // 1/sqrt(32)

// ---------------- scratch ----------------
__device__ int      g_bcnt[256];
__device__ int      g_cnt[Bq];
__device__ int      g_idx[NTOK];
__device__ float    g_bsum[Bq];
__device__ float    g_acc[Bq * Dq];
__device__ unsigned g_bar1 = 0u;
__device__ unsigned g_bar2 = 0u;

// ---------------- helpers ----------------
__device__ __forceinline__ void fma2(unsigned long long& d,
                                     unsigned long long a,
                                     unsigned long long b) {
    asm("fma.rn.f32x2 %0, %1, %2, %3;" : "=l"(d) : "l"(a), "l"(b), "l"(d));
}
__device__ __forceinline__ float2 upk(unsigned long long v) {
    float2 r;
    asm("mov.b64 {%0, %1}, %2;" : "=f"(r.x), "=f"(r.y) : "l"(v));
    return r;
}
__device__ __forceinline__ float sigmoidf(float v) {
    return 1.0f / (1.0f + __expf(-v));
}
__device__ __forceinline__ void half_bar(int id) {
    asm volatile("bar.sync %0, 256;" :: "r"(id) : "memory");
}
__device__ __forceinline__ unsigned pack_bf2(float a, float b) {
    __nv_bfloat162 t = __float22bfloat162_rn(make_float2(a, b));
    return *(unsigned*)&t;
}
__device__ __forceinline__ bool mask_on(const void* mask, int mm, int t) {
    if (mm == 1) return ((const int*)mask)[t] != 0;
    if (mm == 2) return ((const float*)mask)[t] != 0.0f;
    return ((const unsigned char*)mask)[t] != 0;
}
__device__ __forceinline__ int detect_mode(const unsigned int* m, int lane) {
    bool ai = true, af = true;
#pragma unroll
    for (int k = 0; k < 8; ++k) {
        unsigned v = m[lane * 8 + k];
        ai &= (v <= 1u);
        af &= (v == 0u || v == 0x3F800000u);
    }
    unsigned bi = __ballot_sync(0xffffffffu, ai);
    unsigned bf = __ballot_sync(0xffffffffu, af);
    return (bi == 0xffffffffu) ? 1 : ((bf == 0xffffffffu) ? 2 : 0);
}

// Monotonic grid barrier (all nb blocks co-resident; counter never resets).
__device__ __forceinline__ void grid_barrier(unsigned* bar, unsigned nb) {
    __syncthreads();
    if (threadIdx.x == 0) {
        __threadfence();
        unsigned r = atomicAdd(bar, 1u);
        unsigned target = (r / nb + 1u) * nb;
        while (*((volatile unsigned*)bar) < target) {}
    }
    __syncthreads();
}

// -------------------- kernel 1: one-pass ordered per-batch compaction ------
__global__ void k_prep(const void* mask) {
    __shared__ int wcnt[8];
    __shared__ int s_mode;
    const int tid = threadIdx.x, bid = blockIdx.x;
    const int lane = tid & 31, wid = tid >> 5;

    if (wid == 0) {
        int md = detect_mode((const unsigned int*)mask, lane);
        if (lane == 0) s_mode = md;
    }
    const int g = bid * 256 + tid;
    if (bid < 64) g_acc[g] = 0.0f;
    if (g < Bq) g_bsum[g] = 0.0f;
    __syncthreads();

    const bool on = mask_on(mask, s_mode, g);
    const unsigned bal = __ballot_sync(0xffffffffu, on);
    if (lane == 0) wcnt[wid] = __popc(bal);
    __syncthreads();

    int btot = 0, wbase = 0;
#pragma unroll
    for (int w = 0; w < 8; ++w) {
        if (w < wid) wbase += wcnt[w];
        btot += wcnt[w];
    }
    if (tid == 0) g_bcnt[bid] = btot;

    grid_barrier(&g_bar1, 256);

    const int b = bid >> 3;
    int off = 0, cnt = 0;
#pragma unroll
    for (int j = 0; j < 8; ++j) {
        int idx = b * 8 + j;
        int v = __ldcg(&g_bcnt[idx]);
        cnt += v;
        if (idx < bid) off += v;
    }
    if (tid == 0) g_cnt[b] = cnt;
    if (on)
        g_idx[b * 2048 + off + wbase + __popc(bal & ((1u << lane) - 1u))] = g;
}

// -------------------- kernel 2: persistent main + fused final --------------
// 512 threads = two independent 8-warp halves; each half owns an X/Ws buffer
// and a named barrier, processing its own slice stream.
__global__ void __launch_bounds__(NT) k_main(const float* __restrict__ inp,
                                             const float* __restrict__ proj,
                                             const float* __restrict__ hid,
                                             const float* __restrict__ ev,
                                             float* __restrict__ out) {
    extern __shared__ float sm[];
    const int tid  = threadIdx.x;
    const int lane = tid & 31;
    const int wid  = tid >> 5;
    const int half = wid >> 3;     // 0 or 1
    const int hw   = wid & 7;      // warp index within half
    const int tg   = lane >> 3;
    const int hg   = lane & 7;
    const int mi   = hw >> 1;      // wmma M-tile
    const int ni   = hw & 1;       // wmma N-tile
    const int barid = 1 + half;

    __nv_bfloat16* Xb = (__nv_bfloat16*)(sm + SM_X16) + half * (64 * XB_STRIDE);
    __nv_bfloat16* Pb = (__nv_bfloat16*)(sm + SM_PT16);
    float* Ws = sm + SM_WS + half * (64 * WS_STRIDE);

    // ---- stage P as bf16: Pb[n][k] = proj[k*32+n] ----
    for (int i = tid; i < Dq * Hq; i += NT) {
        int k = i >> 5, n = i & 31;
        Pb[n * XB_STRIDE + k] = __float2bfloat16(proj[i]);
    }
    // ---- stage Ht (XOR chunk swizzle, proven layout) ----
    for (int i = tid; i < Hq * Hq; i += NT) {
        int k = i >> 5, h = i & 31;
        int c = h >> 2;
        sm[SM_HT + k * 32 + (((c ^ ((k >> 2) & 7)) << 2) | (h & 3))] =
            hid[h * Hq + k];
    }
    const float4 ev4 = ((const float4*)ev)[hg];

    // ---- slice table: inclusive prefix of per-batch slice counts ----
    int* P    = (int*)(sm + SM_TBL);
    int* scnt = (int*)(sm + SM_TBL) + 33;
    if (tid < 32) {
        int c = g_cnt[tid];
        scnt[tid] = c;
        int x = (c + 63) >> 6;
#pragma unroll
        for (int o = 1; o < 32; o <<= 1) {
            int y = __shfl_up_sync(0xffffffffu, x, o);
            if (lane >= o) x += y;
        }
        P[tid + 1] = x;
        if (tid == 0) P[0] = 0;
    }
    __syncthreads();
    const int NS = P[32];

    float* Wwarp = Ws + hw * (8 * WS_STRIDE);

    const float* HtR0 = sm + SM_HT + (hg * 4 + 0) * 32;
    const float* HtR1 = HtR0 + 32;
    const float* HtR2 = HtR1 + 32;
    const float* HtR3 = HtR2 + 32;

    for (int s = blockIdx.x + half * GRID; s < NS; s += 2 * GRID) {
        // ---- map slice -> (batch, local slice) ----
        int b = 0;
        while (s >= P[b + 1]) ++b;
        const int sl  = s - P[b];
        const int cnt = scnt[b];

        // ---- stage 8 token rows as bf16 (lanes hold row indices mod 8) ----
        const int jr = sl * 64 + hw * 8 + (lane & 7);
        const int myidx = g_idx[b * 2048 + min(jr, cnt - 1)];
#pragma unroll
        for (int tt = 0; tt < 8; ++tt) {
            int tok = __shfl_sync(0xffffffffu, myidx, tt);
            // lane covers floats [lane*16, lane*16+16) of the row
            const float4* src = (const float4*)(inp + (size_t)tok * Dq) + lane * 4;
            float4 v0 = src[0], v1 = src[1], v2 = src[2], v3 = src[3];
            uint4 pkA, pkB;
            pkA.x = pack_bf2(v0.x, v0.y); pkA.y = pack_bf2(v0.z, v0.w);
            pkA.z = pack_bf2(v1.x, v1.y); pkA.w = pack_bf2(v1.z, v1.w);
            pkB.x = pack_bf2(v2.x, v2.y); pkB.y = pack_bf2(v2.z, v2.w);
            pkB.z = pack_bf2(v3.x, v3.y); pkB.w = pack_bf2(v3.z, v3.w);
            uint4* dst = (uint4*)(Xb + (hw * 8 + tt) * XB_STRIDE + lane * 16);
            dst[0] = pkA;
            dst[1] = pkB;
        }
        half_bar(barid);

        // ---- projector GEMM: warp (mi,ni) -> Z tile [16 tok x 16 h] ----
        {
            wmma::fragment<wmma::accumulator, 16, 16, 16, float> c;
            wmma::fill_fragment(c, 0.0f);
            const __nv_bfloat16* Abase = Xb + mi * 16 * XB_STRIDE;
            const __nv_bfloat16* Bbase = Pb + ni * 16 * XB_STRIDE;
#pragma unroll 4
            for (int ks = 0; ks < 32; ++ks) {
                wmma::fragment<wmma::matrix_a, 16, 16, 16, __nv_bfloat16,
                               wmma::row_major> a;
                wmma::fragment<wmma::matrix_b, 16, 16, 16, __nv_bfloat16,
                               wmma::col_major> bf;
                wmma::load_matrix_sync(a, Abase + ks * 16, XB_STRIDE);
                wmma::load_matrix_sync(bf, Bbase + ks * 16, XB_STRIDE);
                wmma::mma_sync(c, a, bf, c);
            }
#pragma unroll
            for (int t = 0; t < c.num_elements; ++t)
                c.x[t] = sigmoidf(c.x[t] * RSCALE);
            wmma::store_matrix_sync(Ws + (mi * 16) * WS_STRIDE + ni * 16,
                                    c, WS_STRIDE, wmma::mem_row_major);
        }
        half_bar(barid);

        // ---- hidden layer (fp32 f32x2, proven loop) ----
        unsigned long long acc1[2][4];
#pragma unroll
        for (int a = 0; a < 2; ++a)
#pragma unroll
            for (int b2 = 0; b2 < 4; ++b2) acc1[a][b2] = 0ull;

        const float* w0a = Wwarp + 2 * tg * WS_STRIDE;
        const float* w0b = w0a + WS_STRIDE;
#pragma unroll
        for (int c = 0; c < 8; ++c) {
            const int h0 = c << 2;
            const int po = ((c ^ hg) << 2);
            ulonglong2 wa = *(const ulonglong2*)(w0a + h0);
            ulonglong2 wb = *(const ulonglong2*)(w0b + h0);
            ulonglong2 q0 = *(const ulonglong2*)(HtR0 + po);
            ulonglong2 q1 = *(const ulonglong2*)(HtR1 + po);
            ulonglong2 q2 = *(const ulonglong2*)(HtR2 + po);
            ulonglong2 q3 = *(const ulonglong2*)(HtR3 + po);
            fma2(acc1[0][0], wa.x, q0.x); fma2(acc1[0][0], wa.y, q0.y);
            fma2(acc1[0][1], wa.x, q1.x); fma2(acc1[0][1], wa.y, q1.y);
            fma2(acc1[0][2], wa.x, q2.x); fma2(acc1[0][2], wa.y, q2.y);
            fma2(acc1[0][3], wa.x, q3.x); fma2(acc1[0][3], wa.y, q3.y);
            fma2(acc1[1][0], wb.x, q0.x); fma2(acc1[1][0], wb.y, q0.y);
            fma2(acc1[1][1], wb.x, q1.x); fma2(acc1[1][1], wb.y, q1.y);
            fma2(acc1[1][2], wb.x, q2.x); fma2(acc1[1][2], wb.y, q2.y);
            fma2(acc1[1][3], wb.x, q3.x); fma2(acc1[1][3], wb.y, q3.y);
        }

        // ---- evaluator + final sigmoid + exp; validity gates wf ----
#pragma unroll
        for (int tp = 0; tp < 2; ++tp) {
            float2 a0 = upk(acc1[tp][0]);
            float2 a1 = upk(acc1[tp][1]);
            float2 a2 = upk(acc1[tp][2]);
            float2 a3 = upk(acc1[tp][3]);
            float e = sigmoidf((a0.x + a0.y) * RSCALE) * ev4.x +
                      sigmoidf((a1.x + a1.y) * RSCALE) * ev4.y +
                      sigmoidf((a2.x + a2.y) * RSCALE) * ev4.z +
                      sigmoidf((a3.x + a3.y) * RSCALE) * ev4.w;
            e += __shfl_xor_sync(0xffffffffu, e, 1);
            e += __shfl_xor_sync(0xffffffffu, e, 2);
            e += __shfl_xor_sync(0xffffffffu, e, 4);
            float z = sigmoidf(e * RSCALE);
            const int trow = 2 * tg + tp;
            bool valid = (sl * 64 + hw * 8 + trow) < cnt;
            if (hg == 0)
                Wwarp[trow * WS_STRIDE + 32] = valid ? __expf(z) : 0.0f;
        }
        __syncwarp();

        // ---- epilogue: wf * x via float4 global reads + direct atomics ----
        float4 accv[4];
#pragma unroll
        for (int j = 0; j < 4; ++j) accv[j] = make_float4(0.f, 0.f, 0.f, 0.f);
        float wfs = 0.0f;
#pragma unroll
        for (int tt = 0; tt < 8; ++tt) {
            float wf = Wwarp[tt * WS_STRIDE + 32];
            wfs += wf;
            int tok = __shfl_sync(0xffffffffu, myidx, tt);
            const float4* xg = (const float4*)(inp + (size_t)tok * Dq);
            if (wf != 0.0f) {
#pragma unroll
                for (int j = 0; j < 4; ++j) {
                    float4 v = __ldg(xg + j * 32 + lane);
                    accv[j].x += wf * v.x;
                    accv[j].y += wf * v.y;
                    accv[j].z += wf * v.z;
                    accv[j].w += wf * v.w;
                }
            }
        }
        {
            float* dst = g_acc + b * Dq;
#pragma unroll
            for (int j = 0; j < 4; ++j) {
                int d0 = (j * 32 + lane) * 4;
                atomicAdd(dst + d0 + 0, accv[j].x);
                atomicAdd(dst + d0 + 1, accv[j].y);
                atomicAdd(dst + d0 + 2, accv[j].z);
                atomicAdd(dst + d0 + 3, accv[j].w);
            }
            if (lane == 0) atomicAdd(&g_bsum[b], wfs);
        }
    }

    // ---- fused final: grid barrier, then normalize ----
    grid_barrier(&g_bar2, GRID);
    const int g = blockIdx.x * NT + tid;
    if (g < Bq * Dq)
        out[g] = __ldcg(&g_acc[g]) / (__ldcg(&g_bsum[g >> 9]) + 1e-12f);
}

// -------------------- launcher --------------------
extern "C" void kernel_launch(void* const* d_in, const int* in_sizes, int n_in,
                              void* d_out, int out_size) {
    const float* inp  = (const float*)d_in[0];
    const void*  mask = d_in[1];
    const float* proj = (const float*)d_in[2];
    const float* hid  = (const float*)d_in[3];
    const float* ev   = (const float*)d_in[4];
    float* out = (float*)d_out;

    cudaFuncSetAttribute(k_main, cudaFuncAttributeMaxDynamicSharedMemorySize,
                         SMEM_BYTES);

    k_prep<<<256, 256>>>(mask);
    k_main<<<GRID, NT, SMEM_BYTES>>>(inp, proj, hid, ev, out);
}

// round 10
// speedup vs baseline: 2.1241x; 1.0522x over previous
#include <cuda_runtime.h>
#include <cuda_bf16.h>
#include <mma.h>
#include <cstdint>

using namespace nvcuda;

// Problem constants
#define Bq 32
#define Sq 2048
#define Dq 512
#define Hq 32
#define NTOK (Bq * Sq)        // 65536
#define GRID 152
#define NT   512              // 16 warps = 4 independent streams of 4

// ---------------- shared layout (float offsets) ----------------
#define XB_STRIDE 520             // bf16 row stride (1040B -> 16B bank rotation)
#define WS_STRIDE 40
#define SM_HT    0                // Ht swizzled 32x32                 -> 1024
#define SM_TBL   1024             // ints P[33]+scnt[32], padded       -> 1104
#define SM_SW    1104             // per-stream work slots (4 ints)    -> 1120
#define SM_WS    1120             // Ws[4][32][40]                     -> 6240
#define SM_X16   6240             // X bf16 [4][32][520] (33280 f)     -> 39520
#define SM_PT16  39520            // P bf16 [32][520] (8320 f)         -> 47840
#define SM_FLOATS 47840
#define SMEM_BYTES (SM_FLOATS * 4)   // 191360

#define RSCALE 0.17677669529663687f  // 1/sqrt(32)

// ---------------- scratch ----------------
__device__ int      g_bcnt[256];
__device__ int      g_cnt[Bq];
__device__ int      g_idx[NTOK];
__device__ float    g_bsum[Bq];
__device__ float    g_acc[Bq * Dq];
__device__ unsigned g_bar1 = 0u;
__device__ unsigned g_bar2 = 0u;
__device__ unsigned g_work = 0u;     // dynamic slice counter (reset by k_prep)

// ---------------- helpers ----------------
__device__ __forceinline__ void fma2(unsigned long long& d,
                                     unsigned long long a,
                                     unsigned long long b) {
    asm("fma.rn.f32x2 %0, %1, %2, %3;" : "=l"(d) : "l"(a), "l"(b), "l"(d));
}
__device__ __forceinline__ float2 upk(unsigned long long v) {
    float2 r;
    asm("mov.b64 {%0, %1}, %2;" : "=f"(r.x), "=f"(r.y) : "l"(v));
    return r;
}
__device__ __forceinline__ float sigmoidf(float v) {
    return 1.0f / (1.0f + __expf(-v));
}
__device__ __forceinline__ void stream_bar(int id) {
    asm volatile("bar.sync %0, 128;" :: "r"(id) : "memory");
}
__device__ __forceinline__ unsigned pack_bf2(float a, float b) {
    __nv_bfloat162 t = __float22bfloat162_rn(make_float2(a, b));
    return *(unsigned*)&t;
}
__device__ __forceinline__ bool mask_on(const void* mask, int mm, int t) {
    if (mm == 1) return ((const int*)mask)[t] != 0;
    if (mm == 2) return ((const float*)mask)[t] != 0.0f;
    return ((const unsigned char*)mask)[t] != 0;
}
__device__ __forceinline__ int detect_mode(const unsigned int* m, int lane) {
    bool ai = true, af = true;
#pragma unroll
    for (int k = 0; k < 8; ++k) {
        unsigned v = m[lane * 8 + k];
        ai &= (v <= 1u);
        af &= (v == 0u || v == 0x3F800000u);
    }
    unsigned bi = __ballot_sync(0xffffffffu, ai);
    unsigned bf = __ballot_sync(0xffffffffu, af);
    return (bi == 0xffffffffu) ? 1 : ((bf == 0xffffffffu) ? 2 : 0);
}

// Monotonic grid barrier (all nb blocks co-resident; counter never resets).
__device__ __forceinline__ void grid_barrier(unsigned* bar, unsigned nb) {
    __syncthreads();
    if (threadIdx.x == 0) {
        __threadfence();
        unsigned r = atomicAdd(bar, 1u);
        unsigned target = (r / nb + 1u) * nb;
        while (*((volatile unsigned*)bar) < target) {}
    }
    __syncthreads();
}

// -------------------- kernel 1: one-pass ordered per-batch compaction ------
__global__ void k_prep(const void* mask) {
    __shared__ int wcnt[8];
    __shared__ int s_mode;
    const int tid = threadIdx.x, bid = blockIdx.x;
    const int lane = tid & 31, wid = tid >> 5;

    if (bid == 0 && tid == 0) g_work = 0u;   // reset dynamic scheduler
    if (wid == 0) {
        int md = detect_mode((const unsigned int*)mask, lane);
        if (lane == 0) s_mode = md;
    }
    const int g = bid * 256 + tid;
    if (bid < 64) g_acc[g] = 0.0f;
    if (g < Bq) g_bsum[g] = 0.0f;
    __syncthreads();

    const bool on = mask_on(mask, s_mode, g);
    const unsigned bal = __ballot_sync(0xffffffffu, on);
    if (lane == 0) wcnt[wid] = __popc(bal);
    __syncthreads();

    int btot = 0, wbase = 0;
#pragma unroll
    for (int w = 0; w < 8; ++w) {
        if (w < wid) wbase += wcnt[w];
        btot += wcnt[w];
    }
    if (tid == 0) g_bcnt[bid] = btot;

    grid_barrier(&g_bar1, 256);

    const int b = bid >> 3;
    int off = 0, cnt = 0;
#pragma unroll
    for (int j = 0; j < 8; ++j) {
        int idx = b * 8 + j;
        int v = __ldcg(&g_bcnt[idx]);
        cnt += v;
        if (idx < bid) off += v;
    }
    if (tid == 0) g_cnt[b] = cnt;
    if (on)
        g_idx[b * 2048 + off + wbase + __popc(bal & ((1u << lane) - 1u))] = g;
}

// -------------------- kernel 2: persistent main + fused final --------------
// 512 threads = 4 independent 4-warp streams; each stream owns an X/Ws buffer
// and a named barrier, pulling 32-token slices from a global work counter.
__global__ void __launch_bounds__(NT) k_main(const float* __restrict__ inp,
                                             const float* __restrict__ proj,
                                             const float* __restrict__ hid,
                                             const float* __restrict__ ev,
                                             float* __restrict__ out) {
    extern __shared__ float sm[];
    const int tid    = threadIdx.x;
    const int lane   = tid & 31;
    const int wid    = tid >> 5;
    const int stream = wid >> 2;     // 0..3
    const int hw     = wid & 3;      // warp within stream
    const int t128   = tid & 127;    // thread index within stream
    const int tg     = lane >> 3;
    const int hg     = lane & 7;
    const int mi     = hw >> 1;      // wmma M-tile (token group of 16)
    const int ni     = hw & 1;       // wmma N-tile (h group of 16)
    const int barid  = 1 + stream;

    __nv_bfloat16* Xb = (__nv_bfloat16*)(sm + SM_X16) + stream * (32 * XB_STRIDE);
    __nv_bfloat16* Pb = (__nv_bfloat16*)(sm + SM_PT16);
    float* Ws = sm + SM_WS + stream * (32 * WS_STRIDE);
    volatile int* sW = (volatile int*)(sm + SM_SW);

    // ---- stage P as bf16: Pb[n][k] = proj[k*32+n] ----
    for (int i = tid; i < Dq * Hq; i += NT) {
        int k = i >> 5, n = i & 31;
        Pb[n * XB_STRIDE + k] = __float2bfloat16(proj[i]);
    }
    // ---- stage Ht (XOR chunk swizzle, proven layout) ----
    for (int i = tid; i < Hq * Hq; i += NT) {
        int k = i >> 5, h = i & 31;
        int c = h >> 2;
        sm[SM_HT + k * 32 + (((c ^ ((k >> 2) & 7)) << 2) | (h & 3))] =
            hid[h * Hq + k];
    }
    const float4 ev4 = ((const float4*)ev)[hg];

    // ---- slice table: inclusive prefix of per-batch 32-token slice counts --
    int* P    = (int*)(sm + SM_TBL);
    int* scnt = (int*)(sm + SM_TBL) + 33;
    if (tid < 32) {
        int c = g_cnt[tid];
        scnt[tid] = c;
        int x = (c + 31) >> 5;
#pragma unroll
        for (int o = 1; o < 32; o <<= 1) {
            int y = __shfl_up_sync(0xffffffffu, x, o);
            if (lane >= o) x += y;
        }
        P[tid + 1] = x;
        if (tid == 0) P[0] = 0;
    }
    __syncthreads();
    const int NS = P[32];

    float* Wwarp = Ws + hw * (8 * WS_STRIDE);

    const float* HtR0 = sm + SM_HT + (hg * 4 + 0) * 32;
    const float* HtR1 = HtR0 + 32;
    const float* HtR2 = HtR1 + 32;
    const float* HtR3 = HtR2 + 32;

    for (;;) {
        // ---- grab next slice (dynamic) ----
        if (t128 == 0) sW[stream] = (int)atomicAdd(&g_work, 1u);
        stream_bar(barid);              // work id visible; prev epilogue done
        const int s = sW[stream];
        if (s >= NS) break;

        // ---- map slice -> (batch, local slice) ----
        int b = 0;
        while (s >= P[b + 1]) ++b;
        const int sl  = s - P[b];
        const int cnt = scnt[b];

        // ---- stage 8 token rows as bf16 per warp (lanes hold row idx) ----
        const int jr = sl * 32 + hw * 8 + (lane & 7);
        const int myidx = g_idx[b * 2048 + min(jr, cnt - 1)];
#pragma unroll
        for (int tt = 0; tt < 8; ++tt) {
            int tok = __shfl_sync(0xffffffffu, myidx, tt);
            const float4* src = (const float4*)(inp + (size_t)tok * Dq) + lane * 4;
            float4 v0 = src[0], v1 = src[1], v2 = src[2], v3 = src[3];
            uint4 pkA, pkB;
            pkA.x = pack_bf2(v0.x, v0.y); pkA.y = pack_bf2(v0.z, v0.w);
            pkA.z = pack_bf2(v1.x, v1.y); pkA.w = pack_bf2(v1.z, v1.w);
            pkB.x = pack_bf2(v2.x, v2.y); pkB.y = pack_bf2(v2.z, v2.w);
            pkB.z = pack_bf2(v3.x, v3.y); pkB.w = pack_bf2(v3.z, v3.w);
            uint4* dst = (uint4*)(Xb + (hw * 8 + tt) * XB_STRIDE + lane * 16);
            dst[0] = pkA;
            dst[1] = pkB;
        }
        stream_bar(barid);              // X ready

        // ---- projector GEMM: warp (mi,ni) -> Z tile [16 tok x 16 h] ----
        {
            wmma::fragment<wmma::accumulator, 16, 16, 16, float> c;
            wmma::fill_fragment(c, 0.0f);
            const __nv_bfloat16* Abase = Xb + mi * 16 * XB_STRIDE;
            const __nv_bfloat16* Bbase = Pb + ni * 16 * XB_STRIDE;
#pragma unroll 4
            for (int ks = 0; ks < 32; ++ks) {
                wmma::fragment<wmma::matrix_a, 16, 16, 16, __nv_bfloat16,
                               wmma::row_major> a;
                wmma::fragment<wmma::matrix_b, 16, 16, 16, __nv_bfloat16,
                               wmma::col_major> bf;
                wmma::load_matrix_sync(a, Abase + ks * 16, XB_STRIDE);
                wmma::load_matrix_sync(bf, Bbase + ks * 16, XB_STRIDE);
                wmma::mma_sync(c, a, bf, c);
            }
#pragma unroll
            for (int t = 0; t < c.num_elements; ++t)
                c.x[t] = sigmoidf(c.x[t] * RSCALE);
            wmma::store_matrix_sync(Ws + (mi * 16) * WS_STRIDE + ni * 16,
                                    c, WS_STRIDE, wmma::mem_row_major);
        }
        stream_bar(barid);              // Ws ready

        // ---- hidden layer (fp32 f32x2, proven loop): warp's 8 tokens ----
        unsigned long long acc1[2][4];
#pragma unroll
        for (int a = 0; a < 2; ++a)
#pragma unroll
            for (int b2 = 0; b2 < 4; ++b2) acc1[a][b2] = 0ull;

        const float* w0a = Wwarp + 2 * tg * WS_STRIDE;
        const float* w0b = w0a + WS_STRIDE;
#pragma unroll
        for (int c = 0; c < 8; ++c) {
            const int h0 = c << 2;
            const int po = ((c ^ hg) << 2);
            ulonglong2 wa = *(const ulonglong2*)(w0a + h0);
            ulonglong2 wb = *(const ulonglong2*)(w0b + h0);
            ulonglong2 q0 = *(const ulonglong2*)(HtR0 + po);
            ulonglong2 q1 = *(const ulonglong2*)(HtR1 + po);
            ulonglong2 q2 = *(const ulonglong2*)(HtR2 + po);
            ulonglong2 q3 = *(const ulonglong2*)(HtR3 + po);
            fma2(acc1[0][0], wa.x, q0.x); fma2(acc1[0][0], wa.y, q0.y);
            fma2(acc1[0][1], wa.x, q1.x); fma2(acc1[0][1], wa.y, q1.y);
            fma2(acc1[0][2], wa.x, q2.x); fma2(acc1[0][2], wa.y, q2.y);
            fma2(acc1[0][3], wa.x, q3.x); fma2(acc1[0][3], wa.y, q3.y);
            fma2(acc1[1][0], wb.x, q0.x); fma2(acc1[1][0], wb.y, q0.y);
            fma2(acc1[1][1], wb.x, q1.x); fma2(acc1[1][1], wb.y, q1.y);
            fma2(acc1[1][2], wb.x, q2.x); fma2(acc1[1][2], wb.y, q2.y);
            fma2(acc1[1][3], wb.x, q3.x); fma2(acc1[1][3], wb.y, q3.y);
        }

        // ---- evaluator + final sigmoid + exp; validity gates wf ----
#pragma unroll
        for (int tp = 0; tp < 2; ++tp) {
            float2 a0 = upk(acc1[tp][0]);
            float2 a1 = upk(acc1[tp][1]);
            float2 a2 = upk(acc1[tp][2]);
            float2 a3 = upk(acc1[tp][3]);
            float e = sigmoidf((a0.x + a0.y) * RSCALE) * ev4.x +
                      sigmoidf((a1.x + a1.y) * RSCALE) * ev4.y +
                      sigmoidf((a2.x + a2.y) * RSCALE) * ev4.z +
                      sigmoidf((a3.x + a3.y) * RSCALE) * ev4.w;
            e += __shfl_xor_sync(0xffffffffu, e, 1);
            e += __shfl_xor_sync(0xffffffffu, e, 2);
            e += __shfl_xor_sync(0xffffffffu, e, 4);
            float z = sigmoidf(e * RSCALE);
            const int trow = 2 * tg + tp;
            bool valid = (sl * 32 + hw * 8 + trow) < cnt;
            if (hg == 0)
                Wwarp[trow * WS_STRIDE + 32] = valid ? __expf(z) : 0.0f;
        }
        __syncwarp();

        // ---- epilogue: wf * x via float4 global reads + direct atomics ----
        float4 accv[4];
#pragma unroll
        for (int j = 0; j < 4; ++j) accv[j] = make_float4(0.f, 0.f, 0.f, 0.f);
        float wfs = 0.0f;
#pragma unroll
        for (int tt = 0; tt < 8; ++tt) {
            float wf = Wwarp[tt * WS_STRIDE + 32];
            wfs += wf;
            int tok = __shfl_sync(0xffffffffu, myidx, tt);
            const float4* xg = (const float4*)(inp + (size_t)tok * Dq);
            if (wf != 0.0f) {
#pragma unroll
                for (int j = 0; j < 4; ++j) {
                    float4 v = __ldg(xg + j * 32 + lane);
                    accv[j].x += wf * v.x;
                    accv[j].y += wf * v.y;
                    accv[j].z += wf * v.z;
                    accv[j].w += wf * v.w;
                }
            }
        }
        {
            float* dst = g_acc + b * Dq;
#pragma unroll
            for (int j = 0; j < 4; ++j) {
                int d0 = (j * 32 + lane) * 4;
                atomicAdd(dst + d0 + 0, accv[j].x);
                atomicAdd(dst + d0 + 1, accv[j].y);
                atomicAdd(dst + d0 + 2, accv[j].z);
                atomicAdd(dst + d0 + 3, accv[j].w);
            }
            if (lane == 0 && hg == 0 && tg == 0) { /* no-op shape keeper */ }
            if (lane == 0) atomicAdd(&g_bsum[b], wfs);
        }
    }

    // ---- fused final: grid barrier, then normalize ----
    grid_barrier(&g_bar2, GRID);
    const int g = blockIdx.x * NT + tid;
    if (g < Bq * Dq)
        out[g] = __ldcg(&g_acc[g]) / (__ldcg(&g_bsum[g >> 9]) + 1e-12f);
}

// -------------------- launcher --------------------
extern "C" void kernel_launch(void* const* d_in, const int* in_sizes, int n_in,
                              void* d_out, int out_size) {
    const float* inp  = (const float*)d_in[0];
    const void*  mask = d_in[1];
    const float* proj = (const float*)d_in[2];
    const float* hid  = (const float*)d_in[3];
    const float* ev   = (const float*)d_in[4];
    float* out = (float*)d_out;

    cudaFuncSetAttribute(k_main, cudaFuncAttributeMaxDynamicSharedMemorySize,
                         SMEM_BYTES);

    k_prep<<<256, 256>>>(mask);
    k_main<<<GRID, NT, SMEM_BYTES>>>(inp, proj, hid, ev, out);
}

// round 11
// speedup vs baseline: 2.2857x; 1.0761x over previous
#include <cuda_runtime.h>
#include <cuda_bf16.h>
#include <mma.h>
#include <cstdint>

using namespace nvcuda;

// Problem constants
#define Bq 32
#define Sq 2048
#define Dq 512
#define Hq 32
#define NTOK (Bq * Sq)        // 65536
#define GRID 152
#define NT   512              // 16 warps = 8 independent streams of 2

// ---------------- shared layout (float offsets) ----------------
#define XB_STRIDE 520             // bf16 row stride (1040B -> 16B bank rotation)
#define WS_STRIDE 40
#define SM_HT    0                // Ht swizzled 32x32                 -> 1024
#define SM_TBL   1024             // ints P[33]+scnt[32], padded       -> 1104
#define SM_SW    1104             // per-stream work slots (8 ints)    -> 1120
#define SM_WS    1120             // Ws[8][16][40]                     -> 6240
#define SM_X16   6240             // X bf16 [8][16][520] (33280 f)     -> 39520
#define SM_PT16  39520            // P bf16 [32][520] (8320 f)         -> 47840
#define SM_FLOATS 47840
#define SMEM_BYTES (SM_FLOATS * 4)   // 191360

#define RSCALE 0.17677669529663687f  // 1/sqrt(32)

// ---------------- scratch ----------------
__device__ int      g_bcnt[256];
__device__ int      g_cnt[Bq];
__device__ int      g_idx[NTOK];
__device__ float    g_bsum[Bq];
__device__ float    g_acc[Bq * Dq];
__device__ unsigned g_bar1 = 0u;
__device__ unsigned g_bar2 = 0u;
__device__ unsigned g_work = 0u;     // dynamic slice counter (reset by k_prep)

// ---------------- helpers ----------------
__device__ __forceinline__ void fma2(unsigned long long& d,
                                     unsigned long long a,
                                     unsigned long long b) {
    asm("fma.rn.f32x2 %0, %1, %2, %3;" : "=l"(d) : "l"(a), "l"(b), "l"(d));
}
__device__ __forceinline__ float2 upk(unsigned long long v) {
    float2 r;
    asm("mov.b64 {%0, %1}, %2;" : "=f"(r.x), "=f"(r.y) : "l"(v));
    return r;
}
__device__ __forceinline__ float sigmoidf(float v) {
    return 1.0f / (1.0f + __expf(-v));
}
__device__ __forceinline__ void stream_bar(int id) {
    asm volatile("bar.sync %0, 64;" :: "r"(id) : "memory");
}
__device__ __forceinline__ unsigned pack_bf2(float a, float b) {
    __nv_bfloat162 t = __float22bfloat162_rn(make_float2(a, b));
    return *(unsigned*)&t;
}
__device__ __forceinline__ bool mask_on(const void* mask, int mm, int t) {
    if (mm == 1) return ((const int*)mask)[t] != 0;
    if (mm == 2) return ((const float*)mask)[t] != 0.0f;
    return ((const unsigned char*)mask)[t] != 0;
}
__device__ __forceinline__ int detect_mode(const unsigned int* m, int lane) {
    bool ai = true, af = true;
#pragma unroll
    for (int k = 0; k < 8; ++k) {
        unsigned v = m[lane * 8 + k];
        ai &= (v <= 1u);
        af &= (v == 0u || v == 0x3F800000u);
    }
    unsigned bi = __ballot_sync(0xffffffffu, ai);
    unsigned bf = __ballot_sync(0xffffffffu, af);
    return (bi == 0xffffffffu) ? 1 : ((bf == 0xffffffffu) ? 2 : 0);
}

// Monotonic grid barrier (all nb blocks co-resident; counter never resets).
__device__ __forceinline__ void grid_barrier(unsigned* bar, unsigned nb) {
    __syncthreads();
    if (threadIdx.x == 0) {
        __threadfence();
        unsigned r = atomicAdd(bar, 1u);
        unsigned target = (r / nb + 1u) * nb;
        while (*((volatile unsigned*)bar) < target) {}
    }
    __syncthreads();
}

// -------------------- kernel 1: one-pass ordered per-batch compaction ------
__global__ void k_prep(const void* mask) {
    __shared__ int wcnt[8];
    __shared__ int s_mode;
    const int tid = threadIdx.x, bid = blockIdx.x;
    const int lane = tid & 31, wid = tid >> 5;

    if (bid == 0 && tid == 0) g_work = 0u;   // reset dynamic scheduler
    if (wid == 0) {
        int md = detect_mode((const unsigned int*)mask, lane);
        if (lane == 0) s_mode = md;
    }
    const int g = bid * 256 + tid;
    if (bid < 64) g_acc[g] = 0.0f;
    if (g < Bq) g_bsum[g] = 0.0f;
    __syncthreads();

    const bool on = mask_on(mask, s_mode, g);
    const unsigned bal = __ballot_sync(0xffffffffu, on);
    if (lane == 0) wcnt[wid] = __popc(bal);
    __syncthreads();

    int btot = 0, wbase = 0;
#pragma unroll
    for (int w = 0; w < 8; ++w) {
        if (w < wid) wbase += wcnt[w];
        btot += wcnt[w];
    }
    if (tid == 0) g_bcnt[bid] = btot;

    grid_barrier(&g_bar1, 256);

    const int b = bid >> 3;
    int off = 0, cnt = 0;
#pragma unroll
    for (int j = 0; j < 8; ++j) {
        int idx = b * 8 + j;
        int v = __ldcg(&g_bcnt[idx]);
        cnt += v;
        if (idx < bid) off += v;
    }
    if (tid == 0) g_cnt[b] = cnt;
    if (on)
        g_idx[b * 2048 + off + wbase + __popc(bal & ((1u << lane) - 1u))] = g;
}

// -------------------- kernel 2: persistent main + fused final --------------
// 512 threads = 8 independent 2-warp streams; each stream owns an X/Ws buffer
// and a named barrier, pulling 16-token slices from a global work counter.
__global__ void __launch_bounds__(NT) k_main(const float* __restrict__ inp,
                                             const float* __restrict__ proj,
                                             const float* __restrict__ hid,
                                             const float* __restrict__ ev,
                                             float* __restrict__ out) {
    extern __shared__ float sm[];
    const int tid    = threadIdx.x;
    const int lane   = tid & 31;
    const int wid    = tid >> 5;
    const int stream = wid >> 1;     // 0..7
    const int hw     = wid & 1;      // warp within stream (= wmma ni)
    const int t64    = tid & 63;     // thread index within stream
    const int tg     = lane >> 3;
    const int hg     = lane & 7;
    const int barid  = 1 + stream;   // named barriers 1..8

    __nv_bfloat16* Xb = (__nv_bfloat16*)(sm + SM_X16) + stream * (16 * XB_STRIDE);
    __nv_bfloat16* Pb = (__nv_bfloat16*)(sm + SM_PT16);
    float* Ws = sm + SM_WS + stream * (16 * WS_STRIDE);
    volatile int* sW = (volatile int*)(sm + SM_SW);

    // ---- stage P as bf16: Pb[n][k] = proj[k*32+n] ----
    for (int i = tid; i < Dq * Hq; i += NT) {
        int k = i >> 5, n = i & 31;
        Pb[n * XB_STRIDE + k] = __float2bfloat16(proj[i]);
    }
    // ---- stage Ht (XOR chunk swizzle, proven layout) ----
    for (int i = tid; i < Hq * Hq; i += NT) {
        int k = i >> 5, h = i & 31;
        int c = h >> 2;
        sm[SM_HT + k * 32 + (((c ^ ((k >> 2) & 7)) << 2) | (h & 3))] =
            hid[h * Hq + k];
    }
    const float4 ev4 = ((const float4*)ev)[hg];

    // ---- slice table: inclusive prefix of per-batch 16-token slice counts --
    int* P    = (int*)(sm + SM_TBL);
    int* scnt = (int*)(sm + SM_TBL) + 33;
    if (tid < 32) {
        int c = g_cnt[tid];
        scnt[tid] = c;
        int x = (c + 15) >> 4;
#pragma unroll
        for (int o = 1; o < 32; o <<= 1) {
            int y = __shfl_up_sync(0xffffffffu, x, o);
            if (lane >= o) x += y;
        }
        P[tid + 1] = x;
        if (tid == 0) P[0] = 0;
    }
    __syncthreads();
    const int NS = P[32];

    float* Wwarp = Ws + hw * (8 * WS_STRIDE);   // own 8 token rows

    const float* HtR0 = sm + SM_HT + (hg * 4 + 0) * 32;
    const float* HtR1 = HtR0 + 32;
    const float* HtR2 = HtR1 + 32;
    const float* HtR3 = HtR2 + 32;

    for (;;) {
        // ---- grab next slice (dynamic) ----
        if (t64 == 0) sW[stream] = (int)atomicAdd(&g_work, 1u);
        stream_bar(barid);              // work id visible; prev epilogue done
        const int s = sW[stream];
        if (s >= NS) break;

        // ---- map slice -> (batch, local slice) ----
        int b = 0;
        while (s >= P[b + 1]) ++b;
        const int sl  = s - P[b];
        const int cnt = scnt[b];

        // ---- stage own 8 token rows as bf16 (lanes hold row idx mod 8) ----
        const int jr = sl * 16 + hw * 8 + (lane & 7);
        const int myidx = g_idx[b * 2048 + min(jr, cnt - 1)];
        // all-16 token view for the epilogue (lane&15)
        const int jr16 = sl * 16 + (lane & 15);
        const int idx16 = g_idx[b * 2048 + min(jr16, cnt - 1)];
#pragma unroll
        for (int tt = 0; tt < 8; ++tt) {
            int tok = __shfl_sync(0xffffffffu, myidx, tt);
            const float4* src = (const float4*)(inp + (size_t)tok * Dq) + lane * 4;
            float4 v0 = src[0], v1 = src[1], v2 = src[2], v3 = src[3];
            uint4 pkA, pkB;
            pkA.x = pack_bf2(v0.x, v0.y); pkA.y = pack_bf2(v0.z, v0.w);
            pkA.z = pack_bf2(v1.x, v1.y); pkA.w = pack_bf2(v1.z, v1.w);
            pkB.x = pack_bf2(v2.x, v2.y); pkB.y = pack_bf2(v2.z, v2.w);
            pkB.z = pack_bf2(v3.x, v3.y); pkB.w = pack_bf2(v3.z, v3.w);
            uint4* dst = (uint4*)(Xb + (hw * 8 + tt) * XB_STRIDE + lane * 16);
            dst[0] = pkA;
            dst[1] = pkB;
        }
        stream_bar(barid);              // X ready (both warps)

        // ---- projector GEMM: warp hw -> Z tile [16 tok x 16 h] ----
        {
            wmma::fragment<wmma::accumulator, 16, 16, 16, float> c;
            wmma::fill_fragment(c, 0.0f);
            const __nv_bfloat16* Bbase = Pb + hw * 16 * XB_STRIDE;
#pragma unroll 4
            for (int ks = 0; ks < 32; ++ks) {
                wmma::fragment<wmma::matrix_a, 16, 16, 16, __nv_bfloat16,
                               wmma::row_major> a;
                wmma::fragment<wmma::matrix_b, 16, 16, 16, __nv_bfloat16,
                               wmma::col_major> bf;
                wmma::load_matrix_sync(a, Xb + ks * 16, XB_STRIDE);
                wmma::load_matrix_sync(bf, Bbase + ks * 16, XB_STRIDE);
                wmma::mma_sync(c, a, bf, c);
            }
#pragma unroll
            for (int t = 0; t < c.num_elements; ++t)
                c.x[t] = sigmoidf(c.x[t] * RSCALE);
            wmma::store_matrix_sync(Ws + hw * 16, c, WS_STRIDE,
                                    wmma::mem_row_major);
        }
        stream_bar(barid);              // full Ws (both ni halves) ready

        // ---- hidden layer (fp32 f32x2, proven loop): warp's 8 tokens ----
        unsigned long long acc1[2][4];
#pragma unroll
        for (int a = 0; a < 2; ++a)
#pragma unroll
            for (int b2 = 0; b2 < 4; ++b2) acc1[a][b2] = 0ull;

        const float* w0a = Wwarp + 2 * tg * WS_STRIDE;
        const float* w0b = w0a + WS_STRIDE;
#pragma unroll
        for (int c = 0; c < 8; ++c) {
            const int h0 = c << 2;
            const int po = ((c ^ hg) << 2);
            ulonglong2 wa = *(const ulonglong2*)(w0a + h0);
            ulonglong2 wb = *(const ulonglong2*)(w0b + h0);
            ulonglong2 q0 = *(const ulonglong2*)(HtR0 + po);
            ulonglong2 q1 = *(const ulonglong2*)(HtR1 + po);
            ulonglong2 q2 = *(const ulonglong2*)(HtR2 + po);
            ulonglong2 q3 = *(const ulonglong2*)(HtR3 + po);
            fma2(acc1[0][0], wa.x, q0.x); fma2(acc1[0][0], wa.y, q0.y);
            fma2(acc1[0][1], wa.x, q1.x); fma2(acc1[0][1], wa.y, q1.y);
            fma2(acc1[0][2], wa.x, q2.x); fma2(acc1[0][2], wa.y, q2.y);
            fma2(acc1[0][3], wa.x, q3.x); fma2(acc1[0][3], wa.y, q3.y);
            fma2(acc1[1][0], wb.x, q0.x); fma2(acc1[1][0], wb.y, q0.y);
            fma2(acc1[1][1], wb.x, q1.x); fma2(acc1[1][1], wb.y, q1.y);
            fma2(acc1[1][2], wb.x, q2.x); fma2(acc1[1][2], wb.y, q2.y);
            fma2(acc1[1][3], wb.x, q3.x); fma2(acc1[1][3], wb.y, q3.y);
        }

        // ---- evaluator + final sigmoid + exp; validity gates wf ----
#pragma unroll
        for (int tp = 0; tp < 2; ++tp) {
            float2 a0 = upk(acc1[tp][0]);
            float2 a1 = upk(acc1[tp][1]);
            float2 a2 = upk(acc1[tp][2]);
            float2 a3 = upk(acc1[tp][3]);
            float e = sigmoidf((a0.x + a0.y) * RSCALE) * ev4.x +
                      sigmoidf((a1.x + a1.y) * RSCALE) * ev4.y +
                      sigmoidf((a2.x + a2.y) * RSCALE) * ev4.z +
                      sigmoidf((a3.x + a3.y) * RSCALE) * ev4.w;
            e += __shfl_xor_sync(0xffffffffu, e, 1);
            e += __shfl_xor_sync(0xffffffffu, e, 2);
            e += __shfl_xor_sync(0xffffffffu, e, 4);
            float z = sigmoidf(e * RSCALE);
            const int trow = 2 * tg + tp;
            bool valid = (sl * 16 + hw * 8 + trow) < cnt;
            if (hg == 0)
                Wwarp[trow * WS_STRIDE + 32] = valid ? __expf(z) : 0.0f;
        }
        __syncwarp();

        // ---- own-8 weight sum -> g_bsum ----
        {
            float wf8 = (lane < 8) ? Wwarp[lane * WS_STRIDE + 32] : 0.0f;
#pragma unroll
            for (int o = 4; o; o >>= 1)
                wf8 += __shfl_xor_sync(0xffffffffu, wf8, o);
            if (lane == 0) atomicAdd(&g_bsum[b], wf8);
        }
        stream_bar(barid);              // all 16 wf visible to both warps

        // ---- epilogue: warp hw covers d-half [hw*256, hw*256+256) over all
        //      16 tokens; 1 atomic per output element ----
        {
            float4 accv0 = make_float4(0.f, 0.f, 0.f, 0.f);
            float4 accv1 = make_float4(0.f, 0.f, 0.f, 0.f);
#pragma unroll
            for (int tt = 0; tt < 16; ++tt) {
                float wf = Ws[tt * WS_STRIDE + 32];
                if (wf != 0.0f) {
                    int tok = __shfl_sync(0xffffffffu, idx16, tt);
                    const float4* xg = (const float4*)(inp + (size_t)tok * Dq)
                                       + hw * 64 + lane;
                    float4 v0 = __ldg(xg);
                    float4 v1 = __ldg(xg + 32);
                    accv0.x += wf * v0.x; accv0.y += wf * v0.y;
                    accv0.z += wf * v0.z; accv0.w += wf * v0.w;
                    accv1.x += wf * v1.x; accv1.y += wf * v1.y;
                    accv1.z += wf * v1.z; accv1.w += wf * v1.w;
                }
            }
            float* dst = g_acc + b * Dq + hw * 256;
            int d0 = lane * 4;
            atomicAdd(dst + d0 + 0, accv0.x);
            atomicAdd(dst + d0 + 1, accv0.y);
            atomicAdd(dst + d0 + 2, accv0.z);
            atomicAdd(dst + d0 + 3, accv0.w);
            atomicAdd(dst + 128 + d0 + 0, accv1.x);
            atomicAdd(dst + 128 + d0 + 1, accv1.y);
            atomicAdd(dst + 128 + d0 + 2, accv1.z);
            atomicAdd(dst + 128 + d0 + 3, accv1.w);
        }
    }

    // ---- fused final: grid barrier, then normalize ----
    grid_barrier(&g_bar2, GRID);
    const int g = blockIdx.x * NT + tid;
    if (g < Bq * Dq)
        out[g] = __ldcg(&g_acc[g]) / (__ldcg(&g_bsum[g >> 9]) + 1e-12f);
}

// -------------------- launcher --------------------
extern "C" void kernel_launch(void* const* d_in, const int* in_sizes, int n_in,
                              void* d_out, int out_size) {
    const float* inp  = (const float*)d_in[0];
    const void*  mask = d_in[1];
    const float* proj = (const float*)d_in[2];
    const float* hid  = (const float*)d_in[3];
    const float* ev   = (const float*)d_in[4];
    float* out = (float*)d_out;

    cudaFuncSetAttribute(k_main, cudaFuncAttributeMaxDynamicSharedMemorySize,
                         SMEM_BYTES);

    k_prep<<<256, 256>>>(mask);
    k_main<<<GRID, NT, SMEM_BYTES>>>(inp, proj, hid, ev, out);
}